// round 7
// baseline (speedup 1.0000x reference)
#include <cuda_runtime.h>
#include <cuda_bf16.h>

#define B_    16
#define C_    512
#define N_    1681
#define CK_   256
#define MPQ_  1792          // Q/K n-padding (14*128)
#define MP2_  1728          // attention m-padding (54*32)
#define XP_   1792          // x-split padding
#define NTT_  14
#define SCALE_ 0.0625f
#define EPS_  1e-5f

// ---------------- device scratch ----------------
__device__ __nv_bfloat16 g_Qhi[(size_t)B_*CK_*MPQ_];
__device__ __nv_bfloat16 g_Khi[(size_t)B_*CK_*MPQ_];
__device__ __nv_bfloat16 g_Xhi[(size_t)B_*C_*XP_],  g_Xlo[(size_t)B_*C_*XP_];
__device__ float g_S[(size_t)B_*N_*MP2_];
__device__ __nv_bfloat16 g_AHi[(size_t)B_*N_*MP2_], g_ALo[(size_t)B_*N_*MP2_];
__device__ float g_pmin[B_*NTT_*N_], g_pss[B_*NTT_*N_], g_pfs[B_*NTT_*N_];
__device__ float g_inv[B_*N_], g_minv[B_*N_];

// ---------------- helpers ----------------
__device__ __forceinline__ unsigned s2u(const void* p) {
    unsigned a;
    asm("{ .reg .u64 t; cvta.to.shared.u64 t, %1; cvt.u32.u64 %0, t; }" : "=r"(a) : "l"(p));
    return a;
}
__device__ __forceinline__ void ldsm4(unsigned* r, unsigned a) {
    asm volatile("ldmatrix.sync.aligned.m8n8.x4.shared.b16 {%0,%1,%2,%3}, [%4];"
                 : "=r"(r[0]), "=r"(r[1]), "=r"(r[2]), "=r"(r[3]) : "r"(a));
}
__device__ __forceinline__ void ldsm4t(unsigned* r, unsigned a) {
    asm volatile("ldmatrix.sync.aligned.m8n8.x4.trans.shared.b16 {%0,%1,%2,%3}, [%4];"
                 : "=r"(r[0]), "=r"(r[1]), "=r"(r[2]), "=r"(r[3]) : "r"(a));
}
__device__ __forceinline__ void mma_bf(float* c, const unsigned* a, unsigned b0, unsigned b1) {
    asm volatile("mma.sync.aligned.m16n8k16.row.col.f32.bf16.bf16.f32 "
                 "{%0,%1,%2,%3}, {%4,%5,%6,%7}, {%8,%9}, {%0,%1,%2,%3};"
                 : "+f"(c[0]), "+f"(c[1]), "+f"(c[2]), "+f"(c[3])
                 : "r"(a[0]), "r"(a[1]), "r"(a[2]), "r"(a[3]), "r"(b0), "r"(b1));
}
// direct tile: [row128][kd32] bf16, stride 80B. trans tile: [kd32][col128] bf16, stride 272B.
__device__ __forceinline__ void ldA_dir(unsigned* a, unsigned tb, int mb, int ks, int L) {
    int q = L >> 3, rs = L & 7;
    ldsm4(a, tb + (unsigned)((mb + (q & 1) * 8 + rs) * 80 + (ks * 2 + (q >> 1)) * 16));
}
__device__ __forceinline__ void ldA_trn(unsigned* a, unsigned tb, int mb, int ks, int L) {
    int q = L >> 3, rs = L & 7;
    ldsm4t(a, tb + (unsigned)((ks * 16 + (q >> 1) * 8 + rs) * 272 + (mb + (q & 1) * 8) * 2));
}
__device__ __forceinline__ void ldB_dir(unsigned* b, unsigned tb, int nb, int ks, int L) {
    int q = L >> 3, rs = L & 7;
    ldsm4(b, tb + (unsigned)((nb + (q >> 1) * 8 + rs) * 80 + (ks * 2 + (q & 1)) * 16));
}
__device__ __forceinline__ void ldB_trn(unsigned* b, unsigned tb, int nb, int ks, int L) {
    int q = L >> 3, rs = L & 7;
    ldsm4t(b, tb + (unsigned)((ks * 16 + (q & 1) * 8 + rs) * 272 + (nb + (q >> 1) * 8) * 2));
}
__device__ __forceinline__ void split_pack(float a0, float a1, unsigned& hi, unsigned& lo) {
    __nv_bfloat162 h, l;
    h.x = __float2bfloat16_rn(a0); h.y = __float2bfloat16_rn(a1);
    l.x = __float2bfloat16_rn(a0 - __bfloat162float(h.x));
    l.y = __float2bfloat16_rn(a1 - __bfloat162float(h.y));
    hi = *(unsigned*)&h; lo = *(unsigned*)&l;
}
__device__ __forceinline__ unsigned pack_hi(float a0, float a1) {
    __nv_bfloat162 h;
    h.x = __float2bfloat16_rn(a0); h.y = __float2bfloat16_rn(a1);
    return *(unsigned*)&h;
}

// 3-product split chunk (hi/lo both operands)
template<int AT, int BT>
__device__ __forceinline__ void gemm_chunk(float (*acc)[4][4], unsigned ah, unsigned al,
                                           unsigned bh, unsigned bl, int wm, int wn, int L)
{
    #pragma unroll
    for (int ks = 0; ks < 2; ks++) {
        unsigned aH[16], aL[16], bH[8], bL[8];
        #pragma unroll
        for (int fm = 0; fm < 4; fm++) {
            int mb = wm * 64 + fm * 16;
            if (AT) { ldA_trn(aH + fm*4, ah, mb, ks, L); ldA_trn(aL + fm*4, al, mb, ks, L); }
            else    { ldA_dir(aH + fm*4, ah, mb, ks, L); ldA_dir(aL + fm*4, al, mb, ks, L); }
        }
        #pragma unroll
        for (int fp = 0; fp < 2; fp++) {
            int nb = wn * 32 + fp * 16;
            if (BT) { ldB_trn(bH + fp*4, bh, nb, ks, L); ldB_trn(bL + fp*4, bl, nb, ks, L); }
            else    { ldB_dir(bH + fp*4, bh, nb, ks, L); ldB_dir(bL + fp*4, bl, nb, ks, L); }
        }
        #pragma unroll
        for (int fm = 0; fm < 4; fm++)
            #pragma unroll
            for (int fn = 0; fn < 4; fn++) {
                int bi = (fn >> 1) * 4 + (fn & 1) * 2;
                mma_bf(acc[fm][fn], aH + fm*4, bH[bi], bH[bi+1]);
                mma_bf(acc[fm][fn], aH + fm*4, bL[bi], bL[bi+1]);
                mma_bf(acc[fm][fn], aL + fm*4, bH[bi], bH[bi+1]);
            }
    }
}

// 1-product pure bf16 chunk
template<int AT, int BT>
__device__ __forceinline__ void gemm_chunk1(float (*acc)[4][4], unsigned ah,
                                            unsigned bh, int wm, int wn, int L)
{
    #pragma unroll
    for (int ks = 0; ks < 2; ks++) {
        unsigned aH[16], bH[8];
        #pragma unroll
        for (int fm = 0; fm < 4; fm++) {
            int mb = wm * 64 + fm * 16;
            if (AT) ldA_trn(aH + fm*4, ah, mb, ks, L);
            else    ldA_dir(aH + fm*4, ah, mb, ks, L);
        }
        #pragma unroll
        for (int fp = 0; fp < 2; fp++) {
            int nb = wn * 32 + fp * 16;
            if (BT) ldB_trn(bH + fp*4, bh, nb, ks, L);
            else    ldB_dir(bH + fp*4, bh, nb, ks, L);
        }
        #pragma unroll
        for (int fm = 0; fm < 4; fm++)
            #pragma unroll
            for (int fn = 0; fn < 4; fn++) {
                int bi = (fn >> 1) * 4 + (fn & 1) * 2;
                mma_bf(acc[fm][fn], aH + fm*4, bH[bi], bH[bi+1]);
            }
    }
}

// ============ vprep: split x into padded bf16 hi/lo [b][c][XP_] ============
__global__ __launch_bounds__(256)
void vprep(const float* __restrict__ x)
{
    int row = blockIdx.x;                 // b*C + c
    size_t xb = (size_t)row * N_, ob = (size_t)row * XP_;
    for (int m = threadIdx.x; m < XP_; m += 256) {
        float v = (m < N_) ? __ldg(x + xb + m) : 0.f;
        __nv_bfloat16 h = __float2bfloat16_rn(v);
        g_Xhi[ob + m] = h;
        g_Xlo[ob + m] = __float2bfloat16_rn(v - __bfloat162float(h));
    }
}

// ============ proj: D[k,n] = W@x + b (pure bf16), store hi [b][k][n-pad] ============
__global__ __launch_bounds__(256)
void proj_t(const float* __restrict__ Wq, const float* __restrict__ bq,
            const float* __restrict__ Wk, const float* __restrict__ bk)
{
    __shared__ __align__(16) char sm[10240 + 8704];
    unsigned sA = s2u(sm), sB = sA + 10240;
    int t = threadIdx.x, L = t & 31, w = t >> 5, wm = w & 1, wn = w >> 1;
    int z = blockIdx.z, b = z >> 1, isK = z & 1;
    const float* W    = isK ? Wk : Wq;
    const float* bias = isK ? bk : bq;
    __nv_bfloat16* Ohi = isK ? g_Khi : g_Qhi;
    int n0 = blockIdx.x * 128, k0 = blockIdx.y * 128;
    const __nv_bfloat16* Xh = g_Xhi + (size_t)b * C_ * XP_;

    float acc[4][4][4] = {};
    for (int c0 = 0; c0 < C_; c0 += 32) {
        {   // A = W rows k (coalesced float4 -> bf16 hi)
            int r = t >> 1, hf = t & 1;
            const float4* Wp = (const float4*)(W + (size_t)(k0 + r) * C_ + c0 + hf * 16);
            unsigned hi[8];
            #pragma unroll
            for (int v = 0; v < 4; v++) {
                float4 f = Wp[v];
                hi[2*v]   = pack_hi(f.x, f.y);
                hi[2*v+1] = pack_hi(f.z, f.w);
            }
            unsigned off = r * 80 + hf * 32;
            *(uint4*)(sm + off)      = ((uint4*)hi)[0];
            *(uint4*)(sm + off + 16) = ((uint4*)hi)[1];
        }
        {   // B = x rows c, trans layout — pure uint4 copies from pre-split hi
            int r = t >> 3, seg = t & 7;
            size_t src = (size_t)(c0 + r) * XP_ + n0 + seg * 16;
            unsigned off = 10240 + r * 272 + seg * 32;
            *(uint4*)(sm + off)      = *(const uint4*)(Xh + src);
            *(uint4*)(sm + off + 16) = *(const uint4*)(Xh + src + 8);
        }
        __syncthreads();
        gemm_chunk1<0, 1>(acc, sA, sB, wm, wn, L);
        __syncthreads();
    }
    #pragma unroll
    for (int fm = 0; fm < 4; fm++) {
        #pragma unroll
        for (int rh = 0; rh < 2; rh++) {
            int k = k0 + wm * 64 + fm * 16 + (L >> 2) + rh * 8;
            float bia = bias[k];
            #pragma unroll
            for (int fn = 0; fn < 4; fn++) {
                int n = n0 + wn * 32 + fn * 8 + 2 * (L & 3);
                unsigned hp = pack_hi(acc[fm][fn][rh*2] + bia, acc[fm][fn][rh*2+1] + bia);
                *(unsigned*)(Ohi + ((size_t)b * CK_ + k) * MPQ_ + n) = hp;
            }
        }
    }
}

// ============ sim: S[n,m] = (Q.K^T)*scale*fg + row stats (pure bf16 MMA) ============
__global__ __launch_bounds__(256)
void sim_t(const float* __restrict__ fg)
{
    __shared__ __align__(16) char sm[17408 + 6144];
    unsigned sQ = s2u(sm), sK = sQ + 8704;
    float* red = (float*)(sm + 17408);     // [3][8][64]
    int t = threadIdx.x, L = t & 31, w = t >> 5, wm = w & 1, wn = w >> 1;
    int b = blockIdx.z, m0 = blockIdx.x * 128, n0 = blockIdx.y * 128;

    float acc[4][4][4] = {};
    for (int k0 = 0; k0 < CK_; k0 += 32) {
        int tile = t >> 7;               // 0:Q 1:K
        int r = (t & 127) >> 2;          // 32 rows k
        int seg = t & 3;                 // 4 segs of 64B
        const __nv_bfloat16* arr = tile ? g_Khi : g_Qhi;
        int colb = tile ? m0 : n0;
        size_t src = ((size_t)b * CK_ + k0 + r) * MPQ_ + colb + seg * 32;
        unsigned off = tile * 8704 + r * 272 + seg * 64;
        *(uint4*)(sm + off)      = *(const uint4*)(arr + src);
        *(uint4*)(sm + off + 16) = *(const uint4*)(arr + src + 8);
        *(uint4*)(sm + off + 32) = *(const uint4*)(arr + src + 16);
        *(uint4*)(sm + off + 48) = *(const uint4*)(arr + src + 24);
        __syncthreads();
        gemm_chunk1<1, 1>(acc, sQ, sK, wm, wn, L);
        __syncthreads();
    }

    float rmn[4][2], rss[4][2], rfs[4][2];
    #pragma unroll
    for (int fm = 0; fm < 4; fm++)
        #pragma unroll
        for (int rh = 0; rh < 2; rh++) { rmn[fm][rh] = 3.4e38f; rss[fm][rh] = 0.f; rfs[fm][rh] = 0.f; }

    #pragma unroll
    for (int fm = 0; fm < 4; fm++)
        #pragma unroll
        for (int rh = 0; rh < 2; rh++) {
            int n = n0 + wm * 64 + fm * 16 + (L >> 2) + rh * 8;
            if (n < N_) {
                size_t fb = (size_t)b * N_ * N_ + (size_t)n * N_;
                size_t sbv = (size_t)b * N_ * MP2_ + (size_t)n * MP2_;
                #pragma unroll
                for (int fn = 0; fn < 4; fn++)
                    #pragma unroll
                    for (int e = 0; e < 2; e++) {
                        int m = m0 + wn * 32 + fn * 8 + 2 * (L & 3) + e;
                        if (m < N_) {
                            float f = __ldg(fg + fb + m);
                            float s1 = acc[fm][fn][rh*2 + e] * SCALE_ * f;
                            g_S[sbv + m] = s1;
                            rmn[fm][rh] = fminf(rmn[fm][rh], s1);
                            rss[fm][rh] += s1 * f;
                            rfs[fm][rh] += f;
                        }
                    }
            }
        }
    #pragma unroll
    for (int fm = 0; fm < 4; fm++)
        #pragma unroll
        for (int rh = 0; rh < 2; rh++) {
            #pragma unroll
            for (int xr = 1; xr < 4; xr <<= 1) {
                rmn[fm][rh] = fminf(rmn[fm][rh], __shfl_xor_sync(0xFFFFFFFFu, rmn[fm][rh], xr));
                rss[fm][rh] += __shfl_xor_sync(0xFFFFFFFFu, rss[fm][rh], xr);
                rfs[fm][rh] += __shfl_xor_sync(0xFFFFFFFFu, rfs[fm][rh], xr);
            }
            if ((L & 3) == 0) {
                int ri = w * 64 + fm * 16 + rh * 8 + (L >> 2);
                red[ri] = rmn[fm][rh];
                red[512 + ri] = rss[fm][rh];
                red[1024 + ri] = rfs[fm][rh];
            }
        }
    __syncthreads();
    if (t < 128) {
        int hf = t >> 6, row = t & 63;
        float mn = 3.4e38f, ss = 0.f, fs = 0.f;
        #pragma unroll
        for (int j = 0; j < 4; j++) {
            int ww = hf + 2 * j;
            mn = fminf(mn, red[ww * 64 + row]);
            ss += red[512 + ww * 64 + row];
            fs += red[1024 + ww * 64 + row];
        }
        int n = n0 + hf * 64 + row;
        if (n < N_) {
            size_t idx = ((size_t)b * NTT_ + blockIdx.x) * N_ + n;
            g_pmin[idx] = mn; g_pss[idx] = ss; g_pfs[idx] = fs;
        }
    }
}

// ============ fin_stats ============
__global__ __launch_bounds__(256)
void fin_stats()
{
    int i = blockIdx.x * blockDim.x + threadIdx.x;
    if (i >= B_ * N_) return;
    int b = i / N_, n = i - b * N_;
    float mn = 3.4e38f, ss = 0.f, fs = 0.f;
    #pragma unroll 1
    for (int tile = 0; tile < NTT_; tile++) {
        size_t idx = ((size_t)b * NTT_ + tile) * N_ + n;
        mn = fminf(mn, g_pmin[idx]);
        ss += g_pss[idx];
        fs += g_pfs[idx];
    }
    g_inv[i] = 1.f / ((ss - mn * fs) + EPS_);
    g_minv[i] = mn;
}

// ============ xform: attn = (S-min)*fg*inv + bg, split bf16, zero-pad ============
__global__ __launch_bounds__(256)
void xform(const float* __restrict__ fg, const float* __restrict__ bg)
{
    int r = blockIdx.x;               // b*N_ + n
    float mn = g_minv[r], iv = g_inv[r];
    size_t sbase = (size_t)r * MP2_;
    size_t gbase = (size_t)r * N_;
    for (int m = threadIdx.x; m < MP2_; m += 256) {
        float a = 0.f;
        if (m < N_) {
            float s1 = g_S[sbase + m];
            float f  = __ldg(fg + gbase + m);
            float g  = __ldg(bg + gbase + m);
            a = (s1 - mn) * f * iv + g;
        }
        __nv_bfloat16 h = __float2bfloat16_rn(a);
        g_AHi[sbase + m] = h;
        g_ALo[sbase + m] = __float2bfloat16_rn(a - __bfloat162float(h));
    }
}

// ============ ctx: out[c,n] = gamma*(attn @ x^T)[n,c] + x[c,n] (3-product) ============
__global__ __launch_bounds__(256)
void ctx_t(const float* __restrict__ x, const float* __restrict__ gamma,
           float* __restrict__ out)
{
    __shared__ __align__(16) char sm[40960];
    unsigned sA = s2u(sm), sAl = sA + 10240, sB = sA + 20480, sBl = sA + 30720;
    int t = threadIdx.x, L = t & 31, w = t >> 5, wm = w & 1, wn = w >> 1;
    int b = blockIdx.z, n0 = blockIdx.x * 128, c0 = blockIdx.y * 128;
    const __nv_bfloat16* Xh = g_Xhi + (size_t)b * C_ * XP_;
    const __nv_bfloat16* Xl = g_Xlo + (size_t)b * C_ * XP_;

    float acc[4][4][4] = {};
    for (int m0 = 0; m0 < MP2_; m0 += 32) {
        int r = t >> 1, hf = t & 1;
        {   // A = attn rows n (uint4, zero-pad n>=N rows)
            int n = n0 + r;
            unsigned off = r * 80 + hf * 32;
            if (n < N_) {
                size_t ai = ((size_t)b * N_ + n) * MP2_ + m0 + hf * 16;
                *(uint4*)(sm + off)              = *(const uint4*)(g_AHi + ai);
                *(uint4*)(sm + off + 16)         = *(const uint4*)(g_AHi + ai + 8);
                *(uint4*)(sm + 10240 + off)      = *(const uint4*)(g_ALo + ai);
                *(uint4*)(sm + 10240 + off + 16) = *(const uint4*)(g_ALo + ai + 8);
            } else {
                uint4 z = make_uint4(0, 0, 0, 0);
                *(uint4*)(sm + off) = z; *(uint4*)(sm + off + 16) = z;
                *(uint4*)(sm + 10240 + off) = z; *(uint4*)(sm + 10240 + off + 16) = z;
            }
        }
        {   // B = x rows c — pure uint4 copies from pre-split
            size_t src = (size_t)(c0 + r) * XP_ + m0 + hf * 16;
            unsigned off = 20480 + r * 80 + hf * 32;
            *(uint4*)(sm + off)              = *(const uint4*)(Xh + src);
            *(uint4*)(sm + off + 16)         = *(const uint4*)(Xh + src + 8);
            *(uint4*)(sm + 10240 + off)      = *(const uint4*)(Xl + src);
            *(uint4*)(sm + 10240 + off + 16) = *(const uint4*)(Xl + src + 8);
        }
        __syncthreads();
        gemm_chunk<0, 0>(acc, sA, sAl, sB, sBl, wm, wn, L);
        __syncthreads();
    }

    float gam = __ldg(gamma);
    float* stage = (float*)sm;
    #pragma unroll 1
    for (int ch = 0; ch < 2; ch++) {
        if ((wn >> 1) == ch) {
            #pragma unroll
            for (int fm = 0; fm < 4; fm++)
                #pragma unroll
                for (int fn = 0; fn < 4; fn++)
                    #pragma unroll
                    for (int e = 0; e < 4; e++) {
                        int cl = (wn & 1) * 32 + fn * 8 + 2 * (L & 3) + (e & 1);
                        int nl = wm * 64 + fm * 16 + (L >> 2) + (e >> 1) * 8;
                        stage[cl * 132 + nl] = acc[fm][fn][e];
                    }
        }
        __syncthreads();
        #pragma unroll 1
        for (int rr = 0; rr < 8; rr++) {
            int cc = w * 8 + rr;
            int c = c0 + ch * 64 + cc;
            size_t ob = ((size_t)b * C_ + c) * N_;
            #pragma unroll
            for (int jj = 0; jj < 4; jj++) {
                int n = n0 + jj * 32 + L;
                if (n < N_)
                    out[ob + n] = gam * stage[cc * 132 + jj * 32 + L] + __ldg(x + ob + n);
            }
        }
        __syncthreads();
    }
}

// ============================================================
extern "C" void kernel_launch(void* const* d_in, const int* in_sizes, int n_in,
                              void* d_out, int out_size)
{
    const float* x     = (const float*)d_in[0];
    const float* fg    = (const float*)d_in[1];
    const float* bg    = (const float*)d_in[2];
    const float* Wq    = (const float*)d_in[3];
    const float* bq    = (const float*)d_in[4];
    const float* Wk    = (const float*)d_in[5];
    const float* bk    = (const float*)d_in[6];
    const float* gamma = (const float*)d_in[7];
    float* out = (float*)d_out;

    vprep<<<B_ * C_, 256>>>(x);
    proj_t<<<dim3(14, 2, 32), 256>>>(Wq, bq, Wk, bk);
    sim_t<<<dim3(14, 14, 16), 256>>>(fg);
    fin_stats<<<(B_ * N_ + 255) / 256, 256>>>();
    xform<<<B_ * N_, 256>>>(fg, bg);
    ctx_t<<<dim3(14, 4, 16), 256>>>(x, gamma, out);
}

// round 8
// speedup vs baseline: 1.2392x; 1.2392x over previous
#include <cuda_runtime.h>
#include <cuda_bf16.h>

#define B_    16
#define C_    512
#define N_    1681
#define CK_   256
#define MPQ_  1792          // Q/K n-padding (14*128)
#define MP2_  1728          // attention m-padding (108*16)
#define XP_   1792          // x-split padding
#define NTT_  14
#define SCALE_ 0.0625f
#define EPS_  1e-5f

// ---------------- device scratch ----------------
__device__ __nv_bfloat16 g_Qhi[(size_t)B_*CK_*MPQ_], g_Qlo[(size_t)B_*CK_*MPQ_];
__device__ __nv_bfloat16 g_Khi[(size_t)B_*CK_*MPQ_], g_Klo[(size_t)B_*CK_*MPQ_];
__device__ __nv_bfloat16 g_Xhi[(size_t)B_*C_*XP_],  g_Xlo[(size_t)B_*C_*XP_];
__device__ float g_S[(size_t)B_*N_*MP2_];
__device__ __nv_bfloat16 g_AHi[(size_t)B_*N_*MP2_], g_ALo[(size_t)B_*N_*MP2_];
__device__ float g_pmin[B_*NTT_*N_], g_pss[B_*NTT_*N_], g_pfs[B_*NTT_*N_];
__device__ float g_inv[B_*N_], g_minv[B_*N_];

// ---------------- helpers ----------------
__device__ __forceinline__ unsigned s2u(const void* p) {
    unsigned a;
    asm("{ .reg .u64 t; cvta.to.shared.u64 t, %1; cvt.u32.u64 %0, t; }" : "=r"(a) : "l"(p));
    return a;
}
__device__ __forceinline__ void cpa16(unsigned d, const void* s) {
    asm volatile("cp.async.cg.shared.global [%0], [%1], 16;" :: "r"(d), "l"(s));
}
__device__ __forceinline__ void cpaz16(unsigned d, const void* s, int srcsz) {
    asm volatile("cp.async.cg.shared.global [%0], [%1], 16, %2;" :: "r"(d), "l"(s), "r"(srcsz));
}
__device__ __forceinline__ void cpc() { asm volatile("cp.async.commit_group;" ::: "memory"); }
template<int Nn> __device__ __forceinline__ void cpw() {
    asm volatile("cp.async.wait_group %0;" :: "n"(Nn) : "memory");
}
__device__ __forceinline__ void ldsm4(unsigned* r, unsigned a) {
    asm volatile("ldmatrix.sync.aligned.m8n8.x4.shared.b16 {%0,%1,%2,%3}, [%4];"
                 : "=r"(r[0]), "=r"(r[1]), "=r"(r[2]), "=r"(r[3]) : "r"(a));
}
__device__ __forceinline__ void ldsm4t(unsigned* r, unsigned a) {
    asm volatile("ldmatrix.sync.aligned.m8n8.x4.trans.shared.b16 {%0,%1,%2,%3}, [%4];"
                 : "=r"(r[0]), "=r"(r[1]), "=r"(r[2]), "=r"(r[3]) : "r"(a));
}
__device__ __forceinline__ void mma_bf(float* c, const unsigned* a, unsigned b0, unsigned b1) {
    asm volatile("mma.sync.aligned.m16n8k16.row.col.f32.bf16.bf16.f32 "
                 "{%0,%1,%2,%3}, {%4,%5,%6,%7}, {%8,%9}, {%0,%1,%2,%3};"
                 : "+f"(c[0]), "+f"(c[1]), "+f"(c[2]), "+f"(c[3])
                 : "r"(a[0]), "r"(a[1]), "r"(a[2]), "r"(a[3]), "r"(b0), "r"(b1));
}
// direct tile: [row128][kd32] bf16, stride 80B. trans tile: [kd32][col128] bf16, stride 272B.
__device__ __forceinline__ void ldA_dir(unsigned* a, unsigned tb, int mb, int ks, int L) {
    int q = L >> 3, rs = L & 7;
    ldsm4(a, tb + (unsigned)((mb + (q & 1) * 8 + rs) * 80 + (ks * 2 + (q >> 1)) * 16));
}
__device__ __forceinline__ void ldA_trn(unsigned* a, unsigned tb, int mb, int ks, int L) {
    int q = L >> 3, rs = L & 7;
    ldsm4t(a, tb + (unsigned)((ks * 16 + (q >> 1) * 8 + rs) * 272 + (mb + (q & 1) * 8) * 2));
}
__device__ __forceinline__ void ldB_dir(unsigned* b, unsigned tb, int nb, int ks, int L) {
    int q = L >> 3, rs = L & 7;
    ldsm4(b, tb + (unsigned)((nb + (q >> 1) * 8 + rs) * 80 + (ks * 2 + (q & 1)) * 16));
}
__device__ __forceinline__ void ldB_trn(unsigned* b, unsigned tb, int nb, int ks, int L) {
    int q = L >> 3, rs = L & 7;
    ldsm4t(b, tb + (unsigned)((ks * 16 + (q & 1) * 8 + rs) * 272 + (nb + (q >> 1) * 8) * 2));
}
__device__ __forceinline__ void split_pack(float a0, float a1, unsigned& hi, unsigned& lo) {
    __nv_bfloat162 h, l;
    h.x = __float2bfloat16_rn(a0); h.y = __float2bfloat16_rn(a1);
    l.x = __float2bfloat16_rn(a0 - __bfloat162float(h.x));
    l.y = __float2bfloat16_rn(a1 - __bfloat162float(h.y));
    hi = *(unsigned*)&h; lo = *(unsigned*)&l;
}

// 3-product split chunk (separate hi/lo tiles), kd=32
template<int AT, int BT>
__device__ __forceinline__ void gemm_chunk(float (*acc)[4][4], unsigned ah, unsigned al,
                                           unsigned bh, unsigned bl, int wm, int wn, int L)
{
    #pragma unroll
    for (int ks = 0; ks < 2; ks++) {
        unsigned aH[16], aL[16], bH[8], bL[8];
        #pragma unroll
        for (int fm = 0; fm < 4; fm++) {
            int mb = wm * 64 + fm * 16;
            if (AT) { ldA_trn(aH + fm*4, ah, mb, ks, L); ldA_trn(aL + fm*4, al, mb, ks, L); }
            else    { ldA_dir(aH + fm*4, ah, mb, ks, L); ldA_dir(aL + fm*4, al, mb, ks, L); }
        }
        #pragma unroll
        for (int fp = 0; fp < 2; fp++) {
            int nb = wn * 32 + fp * 16;
            if (BT) { ldB_trn(bH + fp*4, bh, nb, ks, L); ldB_trn(bL + fp*4, bl, nb, ks, L); }
            else    { ldB_dir(bH + fp*4, bh, nb, ks, L); ldB_dir(bL + fp*4, bl, nb, ks, L); }
        }
        #pragma unroll
        for (int fm = 0; fm < 4; fm++)
            #pragma unroll
            for (int fn = 0; fn < 4; fn++) {
                int bi = (fn >> 1) * 4 + (fn & 1) * 2;
                mma_bf(acc[fm][fn], aH + fm*4, bH[bi], bH[bi+1]);
                mma_bf(acc[fm][fn], aH + fm*4, bL[bi], bL[bi+1]);
                mma_bf(acc[fm][fn], aL + fm*4, bH[bi], bH[bi+1]);
            }
    }
}

// 3-product split chunk, kd=16, hi/lo interleaved rows [hi 32B | lo 32B | pad 16B], stride 80
__device__ __forceinline__ void gemm_chunk16(float (*acc)[4][4], unsigned ab, unsigned bb,
                                             int wm, int wn, int L)
{
    unsigned aH[16], aL[16], bH[8], bL[8];
    int q = L >> 3, rs = L & 7;
    #pragma unroll
    for (int fm = 0; fm < 4; fm++) {
        int mb = wm * 64 + fm * 16;
        unsigned base = ab + (unsigned)((mb + (q & 1) * 8 + rs) * 80 + (q >> 1) * 16);
        ldsm4(aH + fm*4, base);
        ldsm4(aL + fm*4, base + 32);
    }
    #pragma unroll
    for (int fp = 0; fp < 2; fp++) {
        int nb = wn * 32 + fp * 16;
        unsigned base = bb + (unsigned)((nb + (q >> 1) * 8 + rs) * 80 + (q & 1) * 16);
        ldsm4(bH + fp*4, base);
        ldsm4(bL + fp*4, base + 32);
    }
    #pragma unroll
    for (int fm = 0; fm < 4; fm++)
        #pragma unroll
        for (int fn = 0; fn < 4; fn++) {
            int bi = (fn >> 1) * 4 + (fn & 1) * 2;
            mma_bf(acc[fm][fn], aH + fm*4, bH[bi], bH[bi+1]);
            mma_bf(acc[fm][fn], aH + fm*4, bL[bi], bL[bi+1]);
            mma_bf(acc[fm][fn], aL + fm*4, bH[bi], bH[bi+1]);
        }
}

// ============ vprep: split x into padded bf16 hi/lo [b][c][XP_] ============
__global__ __launch_bounds__(256)
void vprep(const float* __restrict__ x)
{
    int row = blockIdx.x;                 // b*C + c
    size_t xb = (size_t)row * N_, ob = (size_t)row * XP_;
    for (int m = threadIdx.x; m < XP_; m += 256) {
        float v = (m < N_) ? __ldg(x + xb + m) : 0.f;
        __nv_bfloat16 h = __float2bfloat16_rn(v);
        g_Xhi[ob + m] = h;
        g_Xlo[ob + m] = __float2bfloat16_rn(v - __bfloat162float(h));
    }
}

// ============ proj: D[k,n] = W@x + b, store split [b][k][n-pad] ============
__global__ __launch_bounds__(256)
void proj_t(const float* __restrict__ Wq, const float* __restrict__ bq,
            const float* __restrict__ Wk, const float* __restrict__ bk)
{
    __shared__ __align__(16) char sm[20480 + 17408];
    unsigned sA = s2u(sm), sAl = sA + 10240, sB = sA + 20480, sBl = sB + 8704;
    int t = threadIdx.x, L = t & 31, w = t >> 5, wm = w & 1, wn = w >> 1;
    int z = blockIdx.z, b = z >> 1, isK = z & 1;
    const float* W    = isK ? Wk : Wq;
    const float* bias = isK ? bk : bq;
    __nv_bfloat16* Ohi = isK ? g_Khi : g_Qhi;
    __nv_bfloat16* Olo = isK ? g_Klo : g_Qlo;
    int n0 = blockIdx.x * 128, k0 = blockIdx.y * 128;
    const __nv_bfloat16* Xh = g_Xhi + (size_t)b * C_ * XP_;
    const __nv_bfloat16* Xl = g_Xlo + (size_t)b * C_ * XP_;

    float acc[4][4][4] = {};
    for (int c0 = 0; c0 < C_; c0 += 32) {
        {   // A = W rows k (coalesced float4, split in-loop; W is small)
            int r = t >> 1, hf = t & 1;
            const float4* Wp = (const float4*)(W + (size_t)(k0 + r) * C_ + c0 + hf * 16);
            unsigned hi[8], lo[8];
            #pragma unroll
            for (int v = 0; v < 4; v++) {
                float4 f = Wp[v];
                split_pack(f.x, f.y, hi[2*v], lo[2*v]);
                split_pack(f.z, f.w, hi[2*v+1], lo[2*v+1]);
            }
            unsigned off = r * 80 + hf * 32;
            *(uint4*)(sm + off)              = ((uint4*)hi)[0];
            *(uint4*)(sm + off + 16)         = ((uint4*)hi)[1];
            *(uint4*)(sm + 10240 + off)      = ((uint4*)lo)[0];
            *(uint4*)(sm + 10240 + off + 16) = ((uint4*)lo)[1];
        }
        {   // B = x rows c, trans layout — pure uint4 copies from pre-split
            int r = t >> 3, seg = t & 7;
            size_t src = (size_t)(c0 + r) * XP_ + n0 + seg * 16;
            unsigned off = 20480 + r * 272 + seg * 32;
            *(uint4*)(sm + off)             = *(const uint4*)(Xh + src);
            *(uint4*)(sm + off + 16)        = *(const uint4*)(Xh + src + 8);
            *(uint4*)(sm + 8704 + off)      = *(const uint4*)(Xl + src);
            *(uint4*)(sm + 8704 + off + 16) = *(const uint4*)(Xl + src + 8);
        }
        __syncthreads();
        gemm_chunk<0, 1>(acc, sA, sAl, sB, sBl, wm, wn, L);
        __syncthreads();
    }
    #pragma unroll
    for (int fm = 0; fm < 4; fm++) {
        #pragma unroll
        for (int rh = 0; rh < 2; rh++) {
            int k = k0 + wm * 64 + fm * 16 + (L >> 2) + rh * 8;
            float bia = bias[k];
            #pragma unroll
            for (int fn = 0; fn < 4; fn++) {
                int n = n0 + wn * 32 + fn * 8 + 2 * (L & 3);
                float v0 = acc[fm][fn][rh*2]   + bia;
                float v1 = acc[fm][fn][rh*2+1] + bia;
                unsigned hp, lp;
                split_pack(v0, v1, hp, lp);
                size_t idx = ((size_t)b * CK_ + k) * MPQ_ + n;
                *(unsigned*)(Ohi + idx) = hp;
                *(unsigned*)(Olo + idx) = lp;
            }
        }
    }
}

// ============ sim: S[n,m] = (Q.K^T)*scale*fg + row stats ============
__global__ __launch_bounds__(256)
void sim_t(const float* __restrict__ fg)
{
    __shared__ __align__(16) char sm[34816 + 6144];
    unsigned sQ = s2u(sm), sQl = sQ + 8704, sK = sQ + 17408, sKl = sQ + 26112;
    float* red = (float*)(sm + 34816);     // [3][8][64]
    int t = threadIdx.x, L = t & 31, w = t >> 5, wm = w & 1, wn = w >> 1;
    int b = blockIdx.z, m0 = blockIdx.x * 128, n0 = blockIdx.y * 128;

    float acc[4][4][4] = {};
    for (int k0 = 0; k0 < CK_; k0 += 32) {
        int r = t >> 3, seg = t & 7;
        size_t qi = ((size_t)b * CK_ + k0 + r) * MPQ_ + n0 + seg * 16;
        size_t ki = ((size_t)b * CK_ + k0 + r) * MPQ_ + m0 + seg * 16;
        unsigned off = r * 272 + seg * 32;
        *(uint4*)(sm + off)              = *(const uint4*)(g_Qhi + qi);
        *(uint4*)(sm + off + 16)         = *(const uint4*)(g_Qhi + qi + 8);
        *(uint4*)(sm + 8704  + off)      = *(const uint4*)(g_Qlo + qi);
        *(uint4*)(sm + 8704  + off + 16) = *(const uint4*)(g_Qlo + qi + 8);
        *(uint4*)(sm + 17408 + off)      = *(const uint4*)(g_Khi + ki);
        *(uint4*)(sm + 17408 + off + 16) = *(const uint4*)(g_Khi + ki + 8);
        *(uint4*)(sm + 26112 + off)      = *(const uint4*)(g_Klo + ki);
        *(uint4*)(sm + 26112 + off + 16) = *(const uint4*)(g_Klo + ki + 8);
        __syncthreads();
        gemm_chunk<1, 1>(acc, sQ, sQl, sK, sKl, wm, wn, L);
        __syncthreads();
    }

    float rmn[4][2], rss[4][2], rfs[4][2];
    #pragma unroll
    for (int fm = 0; fm < 4; fm++)
        #pragma unroll
        for (int rh = 0; rh < 2; rh++) { rmn[fm][rh] = 3.4e38f; rss[fm][rh] = 0.f; rfs[fm][rh] = 0.f; }

    #pragma unroll
    for (int fm = 0; fm < 4; fm++)
        #pragma unroll
        for (int rh = 0; rh < 2; rh++) {
            int n = n0 + wm * 64 + fm * 16 + (L >> 2) + rh * 8;
            if (n < N_) {
                size_t fb = (size_t)b * N_ * N_ + (size_t)n * N_;
                size_t sbv = (size_t)b * N_ * MP2_ + (size_t)n * MP2_;
                #pragma unroll
                for (int fn = 0; fn < 4; fn++)
                    #pragma unroll
                    for (int e = 0; e < 2; e++) {
                        int m = m0 + wn * 32 + fn * 8 + 2 * (L & 3) + e;
                        if (m < N_) {
                            float f = __ldg(fg + fb + m);
                            float s1 = acc[fm][fn][rh*2 + e] * SCALE_ * f;
                            g_S[sbv + m] = s1;
                            rmn[fm][rh] = fminf(rmn[fm][rh], s1);
                            rss[fm][rh] += s1 * f;
                            rfs[fm][rh] += f;
                        }
                    }
            }
        }
    #pragma unroll
    for (int fm = 0; fm < 4; fm++)
        #pragma unroll
        for (int rh = 0; rh < 2; rh++) {
            #pragma unroll
            for (int xr = 1; xr < 4; xr <<= 1) {
                rmn[fm][rh] = fminf(rmn[fm][rh], __shfl_xor_sync(0xFFFFFFFFu, rmn[fm][rh], xr));
                rss[fm][rh] += __shfl_xor_sync(0xFFFFFFFFu, rss[fm][rh], xr);
                rfs[fm][rh] += __shfl_xor_sync(0xFFFFFFFFu, rfs[fm][rh], xr);
            }
            if ((L & 3) == 0) {
                int ri = w * 64 + fm * 16 + rh * 8 + (L >> 2);
                red[ri] = rmn[fm][rh];
                red[512 + ri] = rss[fm][rh];
                red[1024 + ri] = rfs[fm][rh];
            }
        }
    __syncthreads();
    if (t < 128) {
        int hf = t >> 6, row = t & 63;
        float mn = 3.4e38f, ss = 0.f, fs = 0.f;
        #pragma unroll
        for (int j = 0; j < 4; j++) {
            int ww = hf + 2 * j;
            mn = fminf(mn, red[ww * 64 + row]);
            ss += red[512 + ww * 64 + row];
            fs += red[1024 + ww * 64 + row];
        }
        int n = n0 + hf * 64 + row;
        if (n < N_) {
            size_t idx = ((size_t)b * NTT_ + blockIdx.x) * N_ + n;
            g_pmin[idx] = mn; g_pss[idx] = ss; g_pfs[idx] = fs;
        }
    }
}

// ============ fin_stats ============
__global__ __launch_bounds__(256)
void fin_stats()
{
    int i = blockIdx.x * blockDim.x + threadIdx.x;
    if (i >= B_ * N_) return;
    int b = i / N_, n = i - b * N_;
    float mn = 3.4e38f, ss = 0.f, fs = 0.f;
    #pragma unroll 1
    for (int tile = 0; tile < NTT_; tile++) {
        size_t idx = ((size_t)b * NTT_ + tile) * N_ + n;
        mn = fminf(mn, g_pmin[idx]);
        ss += g_pss[idx];
        fs += g_pfs[idx];
    }
    g_inv[i] = 1.f / ((ss - mn * fs) + EPS_);
    g_minv[i] = mn;
}

// ============ xform: attn = (S-min)*fg*inv + bg, split bf16, zero-pad ============
__global__ __launch_bounds__(256)
void xform(const float* __restrict__ fg, const float* __restrict__ bg)
{
    int r = blockIdx.x;               // b*N_ + n
    float mn = g_minv[r], iv = g_inv[r];
    size_t sbase = (size_t)r * MP2_;
    size_t gbase = (size_t)r * N_;
    for (int m = threadIdx.x; m < MP2_; m += 256) {
        float a = 0.f;
        if (m < N_) {
            float s1 = g_S[sbase + m];
            float f  = __ldg(fg + gbase + m);
            float g  = __ldg(bg + gbase + m);
            a = (s1 - mn) * f * iv + g;
        }
        __nv_bfloat16 h = __float2bfloat16_rn(a);
        g_AHi[sbase + m] = h;
        g_ALo[sbase + m] = __float2bfloat16_rn(a - __bfloat162float(h));
    }
}

// ============ ctx: out[c,n] = gamma*(attn @ x^T)[n,c] + x[c,n] ============
// kd=16 double-buffered cp.async; 2 x (A 10240 + B 10240) = 40960 B (same as before)
__global__ __launch_bounds__(256)
void ctx_t(const float* __restrict__ x, const float* __restrict__ gamma,
           float* __restrict__ out)
{
    __shared__ __align__(16) char sm[40960];
    unsigned sb = s2u(sm);
    int t = threadIdx.x, L = t & 31, w = t >> 5, wm = w & 1, wn = w >> 1;
    int b = blockIdx.z, n0 = blockIdx.x * 128, c0 = blockIdx.y * 128;
    const __nv_bfloat16* Xh = g_Xhi + (size_t)b * C_ * XP_;
    const __nv_bfloat16* Xl = g_Xlo + (size_t)b * C_ * XP_;

    int r = t >> 1, hf = t & 1;
    int nA = n0 + r;
    int okA = (nA < N_) ? 16 : 0;
    const __nv_bfloat16* Ah = g_AHi + ((size_t)b * N_ + (nA < N_ ? nA : 0)) * MP2_;
    const __nv_bfloat16* Al = g_ALo + ((size_t)b * N_ + (nA < N_ ? nA : 0)) * MP2_;
    const __nv_bfloat16* Bh = Xh + (size_t)(c0 + r) * XP_;
    const __nv_bfloat16* Bl = Xl + (size_t)(c0 + r) * XP_;
    unsigned dA = sb + r * 80 + hf * 16;           // hi at +0, lo at +32
    unsigned dB = sb + 10240 + r * 80 + hf * 16;

    auto issue = [&](int i, int buf) {
        int m0 = i * 16;
        unsigned bo = buf * 20480;
        cpaz16(dA + bo,      Ah + m0 + hf * 8, okA);
        cpaz16(dA + bo + 32, Al + m0 + hf * 8, okA);
        cpa16 (dB + bo,      Bh + m0 + hf * 8);
        cpa16 (dB + bo + 32, Bl + m0 + hf * 8);
    };

    float acc[4][4][4] = {};
    issue(0, 0); cpc();
    const int LCH = MP2_ / 16;   // 108
    for (int i = 0; i < LCH; i++) {
        int buf = i & 1;
        if (i + 1 < LCH) { issue(i + 1, buf ^ 1); cpc(); cpw<1>(); }
        else cpw<0>();
        __syncthreads();
        gemm_chunk16(acc, sb + buf * 20480, sb + buf * 20480 + 10240, wm, wn, L);
        __syncthreads();
    }

    float gam = __ldg(gamma);
    float* stage = (float*)sm;
    #pragma unroll 1
    for (int ch = 0; ch < 2; ch++) {
        if ((wn >> 1) == ch) {
            #pragma unroll
            for (int fm = 0; fm < 4; fm++)
                #pragma unroll
                for (int fn = 0; fn < 4; fn++)
                    #pragma unroll
                    for (int e = 0; e < 4; e++) {
                        int cl = (wn & 1) * 32 + fn * 8 + 2 * (L & 3) + (e & 1);
                        int nl = wm * 64 + fm * 16 + (L >> 2) + (e >> 1) * 8;
                        stage[cl * 132 + nl] = acc[fm][fn][e];
                    }
        }
        __syncthreads();
        #pragma unroll 1
        for (int rr = 0; rr < 8; rr++) {
            int cc = w * 8 + rr;
            int c = c0 + ch * 64 + cc;
            size_t ob = ((size_t)b * C_ + c) * N_;
            #pragma unroll
            for (int jj = 0; jj < 4; jj++) {
                int n = n0 + jj * 32 + L;
                if (n < N_)
                    out[ob + n] = gam * stage[cc * 132 + jj * 32 + L] + __ldg(x + ob + n);
            }
        }
        __syncthreads();
    }
}

// ============================================================
extern "C" void kernel_launch(void* const* d_in, const int* in_sizes, int n_in,
                              void* d_out, int out_size)
{
    const float* x     = (const float*)d_in[0];
    const float* fg    = (const float*)d_in[1];
    const float* bg    = (const float*)d_in[2];
    const float* Wq    = (const float*)d_in[3];
    const float* bq    = (const float*)d_in[4];
    const float* Wk    = (const float*)d_in[5];
    const float* bk    = (const float*)d_in[6];
    const float* gamma = (const float*)d_in[7];
    float* out = (float*)d_out;

    vprep<<<B_ * C_, 256>>>(x);
    proj_t<<<dim3(14, 2, 32), 256>>>(Wq, bq, Wk, bk);
    sim_t<<<dim3(14, 14, 16), 256>>>(fg);
    fin_stats<<<(B_ * N_ + 255) / 256, 256>>>();
    xform<<<B_ * N_, 256>>>(fg, bg);
    ctx_t<<<dim3(14, 4, 16), 256>>>(x, gamma, out);
}

// round 9
// speedup vs baseline: 1.2664x; 1.0219x over previous
#include <cuda_runtime.h>
#include <cuda_bf16.h>

#define B_    16
#define C_    512
#define N_    1681
#define CK_   256
#define MPQ_  1792          // Q/K n-padding (14*128)
#define MP2_  1728          // attention m-padding (54*32)
#define XP_   1792          // x-split padding
#define NTT_  14
#define SCALE_ 0.0625f
#define EPS_  1e-5f

// ---------------- device scratch ----------------
__device__ __nv_bfloat16 g_Qhi[(size_t)B_*CK_*MPQ_], g_Qlo[(size_t)B_*CK_*MPQ_];
__device__ __nv_bfloat16 g_Khi[(size_t)B_*CK_*MPQ_], g_Klo[(size_t)B_*CK_*MPQ_];
__device__ __nv_bfloat16 g_Xhi[(size_t)B_*C_*XP_],  g_Xlo[(size_t)B_*C_*XP_];
__device__ float g_S[(size_t)B_*N_*MP2_];
__device__ __nv_bfloat16 g_AHi[(size_t)B_*N_*MP2_], g_ALo[(size_t)B_*N_*MP2_];
__device__ float g_pmin[B_*NTT_*N_], g_pss[B_*NTT_*N_], g_pfs[B_*NTT_*N_];

// ---------------- helpers ----------------
__device__ __forceinline__ unsigned s2u(const void* p) {
    unsigned a;
    asm("{ .reg .u64 t; cvta.to.shared.u64 t, %1; cvt.u32.u64 %0, t; }" : "=r"(a) : "l"(p));
    return a;
}
__device__ __forceinline__ void ldsm4(unsigned* r, unsigned a) {
    asm volatile("ldmatrix.sync.aligned.m8n8.x4.shared.b16 {%0,%1,%2,%3}, [%4];"
                 : "=r"(r[0]), "=r"(r[1]), "=r"(r[2]), "=r"(r[3]) : "r"(a));
}
__device__ __forceinline__ void ldsm4t(unsigned* r, unsigned a) {
    asm volatile("ldmatrix.sync.aligned.m8n8.x4.trans.shared.b16 {%0,%1,%2,%3}, [%4];"
                 : "=r"(r[0]), "=r"(r[1]), "=r"(r[2]), "=r"(r[3]) : "r"(a));
}
__device__ __forceinline__ void mma_bf(float* c, const unsigned* a, unsigned b0, unsigned b1) {
    asm volatile("mma.sync.aligned.m16n8k16.row.col.f32.bf16.bf16.f32 "
                 "{%0,%1,%2,%3}, {%4,%5,%6,%7}, {%8,%9}, {%0,%1,%2,%3};"
                 : "+f"(c[0]), "+f"(c[1]), "+f"(c[2]), "+f"(c[3])
                 : "r"(a[0]), "r"(a[1]), "r"(a[2]), "r"(a[3]), "r"(b0), "r"(b1));
}
// direct tile: [row128][kd32] bf16, stride 80B. trans tile: [kd32][col128] bf16, stride 272B.
__device__ __forceinline__ void ldA_dir(unsigned* a, unsigned tb, int mb, int ks, int L) {
    int q = L >> 3, rs = L & 7;
    ldsm4(a, tb + (unsigned)((mb + (q & 1) * 8 + rs) * 80 + (ks * 2 + (q >> 1)) * 16));
}
__device__ __forceinline__ void ldA_trn(unsigned* a, unsigned tb, int mb, int ks, int L) {
    int q = L >> 3, rs = L & 7;
    ldsm4t(a, tb + (unsigned)((ks * 16 + (q >> 1) * 8 + rs) * 272 + (mb + (q & 1) * 8) * 2));
}
__device__ __forceinline__ void ldB_dir(unsigned* b, unsigned tb, int nb, int ks, int L) {
    int q = L >> 3, rs = L & 7;
    ldsm4(b, tb + (unsigned)((nb + (q >> 1) * 8 + rs) * 80 + (ks * 2 + (q & 1)) * 16));
}
__device__ __forceinline__ void ldB_trn(unsigned* b, unsigned tb, int nb, int ks, int L) {
    int q = L >> 3, rs = L & 7;
    ldsm4t(b, tb + (unsigned)((ks * 16 + (q & 1) * 8 + rs) * 272 + (nb + (q >> 1) * 8) * 2));
}
__device__ __forceinline__ void split_pack(float a0, float a1, unsigned& hi, unsigned& lo) {
    __nv_bfloat162 h, l;
    h.x = __float2bfloat16_rn(a0); h.y = __float2bfloat16_rn(a1);
    l.x = __float2bfloat16_rn(a0 - __bfloat162float(h.x));
    l.y = __float2bfloat16_rn(a1 - __bfloat162float(h.y));
    hi = *(unsigned*)&h; lo = *(unsigned*)&l;
}

// 3-product split chunk (separate hi/lo tiles), kd=32
template<int AT, int BT>
__device__ __forceinline__ void gemm_chunk(float (*acc)[4][4], unsigned ah, unsigned al,
                                           unsigned bh, unsigned bl, int wm, int wn, int L)
{
    #pragma unroll
    for (int ks = 0; ks < 2; ks++) {
        unsigned aH[16], aL[16], bH[8], bL[8];
        #pragma unroll
        for (int fm = 0; fm < 4; fm++) {
            int mb = wm * 64 + fm * 16;
            if (AT) { ldA_trn(aH + fm*4, ah, mb, ks, L); ldA_trn(aL + fm*4, al, mb, ks, L); }
        else    { ldA_dir(aH + fm*4, ah, mb, ks, L); ldA_dir(aL + fm*4, al, mb, ks, L); }
        }
        #pragma unroll
        for (int fp = 0; fp < 2; fp++) {
            int nb = wn * 32 + fp * 16;
            if (BT) { ldB_trn(bH + fp*4, bh, nb, ks, L); ldB_trn(bL + fp*4, bl, nb, ks, L); }
            else    { ldB_dir(bH + fp*4, bh, nb, ks, L); ldB_dir(bL + fp*4, bl, nb, ks, L); }
        }
        #pragma unroll
        for (int fm = 0; fm < 4; fm++)
            #pragma unroll
            for (int fn = 0; fn < 4; fn++) {
                int bi = (fn >> 1) * 4 + (fn & 1) * 2;
                mma_bf(acc[fm][fn], aH + fm*4, bH[bi], bH[bi+1]);
                mma_bf(acc[fm][fn], aH + fm*4, bL[bi], bL[bi+1]);
                mma_bf(acc[fm][fn], aL + fm*4, bH[bi], bH[bi+1]);
            }
    }
}

// ============ vprep: split x into padded bf16 hi/lo [b][c][XP_] ============
__global__ __launch_bounds__(256)
void vprep(const float* __restrict__ x)
{
    int row = blockIdx.x;                 // b*C + c
    size_t xb = (size_t)row * N_, ob = (size_t)row * XP_;
    for (int m = threadIdx.x; m < XP_; m += 256) {
        float v = (m < N_) ? __ldg(x + xb + m) : 0.f;
        __nv_bfloat16 h = __float2bfloat16_rn(v);
        g_Xhi[ob + m] = h;
        g_Xlo[ob + m] = __float2bfloat16_rn(v - __bfloat162float(h));
    }
}

// ============ proj: D[k,n] = W@x + b, store split [b][k][n-pad] ============
__global__ __launch_bounds__(256, 2)
void proj_t(const float* __restrict__ Wq, const float* __restrict__ bq,
            const float* __restrict__ Wk, const float* __restrict__ bk)
{
    __shared__ __align__(16) char sm[20480 + 17408];
    unsigned sA = s2u(sm), sAl = sA + 10240, sB = sA + 20480, sBl = sB + 8704;
    int t = threadIdx.x, L = t & 31, w = t >> 5, wm = w & 1, wn = w >> 1;
    int z = blockIdx.z, b = z >> 1, isK = z & 1;
    const float* W    = isK ? Wk : Wq;
    const float* bias = isK ? bk : bq;
    __nv_bfloat16* Ohi = isK ? g_Khi : g_Qhi;
    __nv_bfloat16* Olo = isK ? g_Klo : g_Qlo;
    int n0 = blockIdx.x * 128, k0 = blockIdx.y * 128;
    const __nv_bfloat16* Xh = g_Xhi + (size_t)b * C_ * XP_;
    const __nv_bfloat16* Xl = g_Xlo + (size_t)b * C_ * XP_;

    float acc[4][4][4] = {};
    for (int c0 = 0; c0 < C_; c0 += 32) {
        {   // A = W rows k (coalesced float4, split in-loop; W is small)
            int r = t >> 1, hf = t & 1;
            const float4* Wp = (const float4*)(W + (size_t)(k0 + r) * C_ + c0 + hf * 16);
            unsigned hi[8], lo[8];
            #pragma unroll
            for (int v = 0; v < 4; v++) {
                float4 f = Wp[v];
                split_pack(f.x, f.y, hi[2*v], lo[2*v]);
                split_pack(f.z, f.w, hi[2*v+1], lo[2*v+1]);
            }
            unsigned off = r * 80 + hf * 32;
            *(uint4*)(sm + off)              = ((uint4*)hi)[0];
            *(uint4*)(sm + off + 16)         = ((uint4*)hi)[1];
            *(uint4*)(sm + 10240 + off)      = ((uint4*)lo)[0];
            *(uint4*)(sm + 10240 + off + 16) = ((uint4*)lo)[1];
        }
        {   // B = x rows c, trans layout — pure uint4 copies from pre-split
            int r = t >> 3, seg = t & 7;
            size_t src = (size_t)(c0 + r) * XP_ + n0 + seg * 16;
            unsigned off = 20480 + r * 272 + seg * 32;
            *(uint4*)(sm + off)             = *(const uint4*)(Xh + src);
            *(uint4*)(sm + off + 16)        = *(const uint4*)(Xh + src + 8);
            *(uint4*)(sm + 8704 + off)      = *(const uint4*)(Xl + src);
            *(uint4*)(sm + 8704 + off + 16) = *(const uint4*)(Xl + src + 8);
        }
        __syncthreads();
        gemm_chunk<0, 1>(acc, sA, sAl, sB, sBl, wm, wn, L);
        __syncthreads();
    }
    #pragma unroll
    for (int fm = 0; fm < 4; fm++) {
        #pragma unroll
        for (int rh = 0; rh < 2; rh++) {
            int k = k0 + wm * 64 + fm * 16 + (L >> 2) + rh * 8;
            float bia = bias[k];
            #pragma unroll
            for (int fn = 0; fn < 4; fn++) {
                int n = n0 + wn * 32 + fn * 8 + 2 * (L & 3);
                float v0 = acc[fm][fn][rh*2]   + bia;
                float v1 = acc[fm][fn][rh*2+1] + bia;
                unsigned hp, lp;
                split_pack(v0, v1, hp, lp);
                size_t idx = ((size_t)b * CK_ + k) * MPQ_ + n;
                *(unsigned*)(Ohi + idx) = hp;
                *(unsigned*)(Olo + idx) = lp;
            }
        }
    }
}

// ============ sim: S[n,m] = (Q.K^T)*scale*fg + row stats ============
__global__ __launch_bounds__(256, 2)
void sim_t(const float* __restrict__ fg)
{
    __shared__ __align__(16) char sm[34816 + 6144];
    unsigned sQ = s2u(sm), sQl = sQ + 8704, sK = sQ + 17408, sKl = sQ + 26112;
    float* red = (float*)(sm + 34816);     // [3][8][64]
    int t = threadIdx.x, L = t & 31, w = t >> 5, wm = w & 1, wn = w >> 1;
    int b = blockIdx.z, m0 = blockIdx.x * 128, n0 = blockIdx.y * 128;

    float acc[4][4][4] = {};
    for (int k0 = 0; k0 < CK_; k0 += 32) {
        int r = t >> 3, seg = t & 7;
        size_t qi = ((size_t)b * CK_ + k0 + r) * MPQ_ + n0 + seg * 16;
        size_t ki = ((size_t)b * CK_ + k0 + r) * MPQ_ + m0 + seg * 16;
        unsigned off = r * 272 + seg * 32;
        *(uint4*)(sm + off)              = *(const uint4*)(g_Qhi + qi);
        *(uint4*)(sm + off + 16)         = *(const uint4*)(g_Qhi + qi + 8);
        *(uint4*)(sm + 8704  + off)      = *(const uint4*)(g_Qlo + qi);
        *(uint4*)(sm + 8704  + off + 16) = *(const uint4*)(g_Qlo + qi + 8);
        *(uint4*)(sm + 17408 + off)      = *(const uint4*)(g_Khi + ki);
        *(uint4*)(sm + 17408 + off + 16) = *(const uint4*)(g_Khi + ki + 8);
        *(uint4*)(sm + 26112 + off)      = *(const uint4*)(g_Klo + ki);
        *(uint4*)(sm + 26112 + off + 16) = *(const uint4*)(g_Klo + ki + 8);
        __syncthreads();
        gemm_chunk<1, 1>(acc, sQ, sQl, sK, sKl, wm, wn, L);
        __syncthreads();
    }

    float rmn[4][2], rss[4][2], rfs[4][2];
    #pragma unroll
    for (int fm = 0; fm < 4; fm++)
        #pragma unroll
        for (int rh = 0; rh < 2; rh++) { rmn[fm][rh] = 3.4e38f; rss[fm][rh] = 0.f; rfs[fm][rh] = 0.f; }

    #pragma unroll
    for (int fm = 0; fm < 4; fm++)
        #pragma unroll
        for (int rh = 0; rh < 2; rh++) {
            int n = n0 + wm * 64 + fm * 16 + (L >> 2) + rh * 8;
            if (n < N_) {
                size_t fb = (size_t)b * N_ * N_ + (size_t)n * N_;
                size_t sbv = (size_t)b * N_ * MP2_ + (size_t)n * MP2_;
                #pragma unroll
                for (int fn = 0; fn < 4; fn++)
                    #pragma unroll
                    for (int e = 0; e < 2; e++) {
                        int m = m0 + wn * 32 + fn * 8 + 2 * (L & 3) + e;
                        if (m < N_) {
                            float f = __ldg(fg + fb + m);
                            float s1 = acc[fm][fn][rh*2 + e] * SCALE_ * f;
                            g_S[sbv + m] = s1;
                            rmn[fm][rh] = fminf(rmn[fm][rh], s1);
                            rss[fm][rh] += s1 * f;
                            rfs[fm][rh] += f;
                        }
                    }
            }
        }
    #pragma unroll
    for (int fm = 0; fm < 4; fm++)
        #pragma unroll
        for (int rh = 0; rh < 2; rh++) {
            #pragma unroll
            for (int xr = 1; xr < 4; xr <<= 1) {
                rmn[fm][rh] = fminf(rmn[fm][rh], __shfl_xor_sync(0xFFFFFFFFu, rmn[fm][rh], xr));
                rss[fm][rh] += __shfl_xor_sync(0xFFFFFFFFu, rss[fm][rh], xr);
                rfs[fm][rh] += __shfl_xor_sync(0xFFFFFFFFu, rfs[fm][rh], xr);
            }
            if ((L & 3) == 0) {
                int ri = w * 64 + fm * 16 + rh * 8 + (L >> 2);
                red[ri] = rmn[fm][rh];
                red[512 + ri] = rss[fm][rh];
                red[1024 + ri] = rfs[fm][rh];
            }
        }
    __syncthreads();
    if (t < 128) {
        int hf = t >> 6, row = t & 63;
        float mn = 3.4e38f, ss = 0.f, fs = 0.f;
        #pragma unroll
        for (int j = 0; j < 4; j++) {
            int ww = hf + 2 * j;
            mn = fminf(mn, red[ww * 64 + row]);
            ss += red[512 + ww * 64 + row];
            fs += red[1024 + ww * 64 + row];
        }
        int n = n0 + hf * 64 + row;
        if (n < N_) {
            size_t idx = ((size_t)b * NTT_ + blockIdx.x) * N_ + n;
            g_pmin[idx] = mn; g_pss[idx] = ss; g_pfs[idx] = fs;
        }
    }
}

// ============ xform: finalize stats + attn = (S-min)*fg*inv + bg, split bf16 ============
__global__ __launch_bounds__(256)
void xform(const float* __restrict__ fg, const float* __restrict__ bg)
{
    __shared__ float s_mn, s_iv;
    int r = blockIdx.x;               // b*N_ + n
    int t = threadIdx.x;
    int b = r / N_, n = r - b * N_;
    if (t < 32) {
        float mn = 3.4e38f, ss = 0.f, fs = 0.f;
        if (t < NTT_) {
            size_t idx = ((size_t)b * NTT_ + t) * N_ + n;
            mn = g_pmin[idx]; ss = g_pss[idx]; fs = g_pfs[idx];
        }
        #pragma unroll
        for (int xr = 16; xr > 0; xr >>= 1) {
            mn = fminf(mn, __shfl_xor_sync(0xFFFFFFFFu, mn, xr));
            ss += __shfl_xor_sync(0xFFFFFFFFu, ss, xr);
            fs += __shfl_xor_sync(0xFFFFFFFFu, fs, xr);
        }
        if (t == 0) { s_mn = mn; s_iv = 1.f / ((ss - mn * fs) + EPS_); }
    }
    __syncthreads();
    float mn = s_mn, iv = s_iv;
    size_t sbase = (size_t)r * MP2_;
    size_t gbase = (size_t)r * N_;
    for (int m = t; m < MP2_; m += 256) {
        float a = 0.f;
        if (m < N_) {
            float s1 = g_S[sbase + m];
            float f  = __ldg(fg + gbase + m);
            float g  = __ldg(bg + gbase + m);
            a = (s1 - mn) * f * iv + g;
        }
        __nv_bfloat16 h = __float2bfloat16_rn(a);
        g_AHi[sbase + m] = h;
        g_ALo[sbase + m] = __float2bfloat16_rn(a - __bfloat162float(h));
    }
}

// ============ ctx: out[c,n] = gamma*(attn @ x^T)[n,c] + x[c,n] (3-product) ============
__global__ __launch_bounds__(256, 2)
void ctx_t(const float* __restrict__ x, const float* __restrict__ gamma,
           float* __restrict__ out)
{
    __shared__ __align__(16) char sm[40960];
    unsigned sA = s2u(sm), sAl = sA + 10240, sB = sA + 20480, sBl = sA + 30720;
    int t = threadIdx.x, L = t & 31, w = t >> 5, wm = w & 1, wn = w >> 1;
    int b = blockIdx.z, n0 = blockIdx.x * 128, c0 = blockIdx.y * 128;
    const __nv_bfloat16* Xh = g_Xhi + (size_t)b * C_ * XP_;
    const __nv_bfloat16* Xl = g_Xlo + (size_t)b * C_ * XP_;

    float acc[4][4][4] = {};
    for (int m0 = 0; m0 < MP2_; m0 += 32) {
        int r = t >> 1, hf = t & 1;
        {   // A = attn rows n (uint4, zero-pad n>=N rows)
            int n = n0 + r;
            unsigned off = r * 80 + hf * 32;
            if (n < N_) {
                size_t ai = ((size_t)b * N_ + n) * MP2_ + m0 + hf * 16;
                *(uint4*)(sm + off)              = *(const uint4*)(g_AHi + ai);
                *(uint4*)(sm + off + 16)         = *(const uint4*)(g_AHi + ai + 8);
                *(uint4*)(sm + 10240 + off)      = *(const uint4*)(g_ALo + ai);
                *(uint4*)(sm + 10240 + off + 16) = *(const uint4*)(g_ALo + ai + 8);
            } else {
                uint4 z = make_uint4(0, 0, 0, 0);
                *(uint4*)(sm + off) = z; *(uint4*)(sm + off + 16) = z;
                *(uint4*)(sm + 10240 + off) = z; *(uint4*)(sm + 10240 + off + 16) = z;
            }
        }
        {   // B = x rows c — pure uint4 copies from pre-split
            size_t src = (size_t)(c0 + r) * XP_ + m0 + hf * 16;
            unsigned off = 20480 + r * 80 + hf * 32;
            *(uint4*)(sm + off)              = *(const uint4*)(Xh + src);
            *(uint4*)(sm + off + 16)         = *(const uint4*)(Xh + src + 8);
            *(uint4*)(sm + 10240 + off)      = *(const uint4*)(Xl + src);
            *(uint4*)(sm + 10240 + off + 16) = *(const uint4*)(Xl + src + 8);
        }
        __syncthreads();
        gemm_chunk<0, 0>(acc, sA, sAl, sB, sBl, wm, wn, L);
        __syncthreads();
    }

    float gam = __ldg(gamma);
    float* stage = (float*)sm;
    #pragma unroll 1
    for (int ch = 0; ch < 2; ch++) {
        if ((wn >> 1) == ch) {
            #pragma unroll
            for (int fm = 0; fm < 4; fm++)
                #pragma unroll
                for (int fn = 0; fn < 4; fn++)
                    #pragma unroll
                    for (int e = 0; e < 4; e++) {
                        int cl = (wn & 1) * 32 + fn * 8 + 2 * (L & 3) + (e & 1);
                        int nl = wm * 64 + fm * 16 + (L >> 2) + (e >> 1) * 8;
                        stage[cl * 132 + nl] = acc[fm][fn][e];
                    }
        }
        __syncthreads();
        #pragma unroll 1
        for (int rr = 0; rr < 8; rr++) {
            int cc = w * 8 + rr;
            int c = c0 + ch * 64 + cc;
            size_t ob = ((size_t)b * C_ + c) * N_;
            #pragma unroll
            for (int jj = 0; jj < 4; jj++) {
                int n = n0 + jj * 32 + L;
                if (n < N_)
                    out[ob + n] = gam * stage[cc * 132 + jj * 32 + L] + __ldg(x + ob + n);
            }
        }
        __syncthreads();
    }
}

// ============================================================
extern "C" void kernel_launch(void* const* d_in, const int* in_sizes, int n_in,
                              void* d_out, int out_size)
{
    const float* x     = (const float*)d_in[0];
    const float* fg    = (const float*)d_in[1];
    const float* bg    = (const float*)d_in[2];
    const float* Wq    = (const float*)d_in[3];
    const float* bq    = (const float*)d_in[4];
    const float* Wk    = (const float*)d_in[5];
    const float* bk    = (const float*)d_in[6];
    const float* gamma = (const float*)d_in[7];
    float* out = (float*)d_out;

    vprep<<<B_ * C_, 256>>>(x);
    proj_t<<<dim3(14, 2, 32), 256>>>(Wq, bq, Wk, bk);
    sim_t<<<dim3(14, 14, 16), 256>>>(fg);
    xform<<<B_ * N_, 256>>>(fg, bg);
    ctx_t<<<dim3(14, 4, 16), 256>>>(x, gamma, out);
}

// round 10
// speedup vs baseline: 1.3898x; 1.0975x over previous
#include <cuda_runtime.h>
#include <cuda_bf16.h>

#define B_    16
#define C_    512
#define N_    1681
#define CK_   256
#define MPQ_  1792          // Q/K n-padding (14*128)
#define MP2_  1728          // attention m-padding (54*32)
#define XP_   1792          // x-split padding
#define NTT_  14
#define SCALE_ 0.0625f
#define EPS_  1e-5f

// ---------------- device scratch ----------------
__device__ __nv_bfloat16 g_Qhi[(size_t)B_*CK_*MPQ_];
__device__ __nv_bfloat16 g_Khi[(size_t)B_*CK_*MPQ_];
__device__ __nv_bfloat16 g_Xhi[(size_t)B_*C_*XP_],  g_Xlo[(size_t)B_*C_*XP_];
__device__ float g_S[(size_t)B_*N_*MP2_];
__device__ __nv_bfloat16 g_AHi[(size_t)B_*N_*MP2_], g_ALo[(size_t)B_*N_*MP2_];
__device__ float g_pmin[B_*NTT_*N_], g_pss[B_*NTT_*N_], g_pfs[B_*NTT_*N_];

// ---------------- helpers ----------------
__device__ __forceinline__ unsigned s2u(const void* p) {
    unsigned a;
    asm("{ .reg .u64 t; cvta.to.shared.u64 t, %1; cvt.u32.u64 %0, t; }" : "=r"(a) : "l"(p));
    return a;
}
__device__ __forceinline__ void ldsm4(unsigned* r, unsigned a) {
    asm volatile("ldmatrix.sync.aligned.m8n8.x4.shared.b16 {%0,%1,%2,%3}, [%4];"
                 : "=r"(r[0]), "=r"(r[1]), "=r"(r[2]), "=r"(r[3]) : "r"(a));
}
__device__ __forceinline__ void ldsm4t(unsigned* r, unsigned a) {
    asm volatile("ldmatrix.sync.aligned.m8n8.x4.trans.shared.b16 {%0,%1,%2,%3}, [%4];"
                 : "=r"(r[0]), "=r"(r[1]), "=r"(r[2]), "=r"(r[3]) : "r"(a));
}
__device__ __forceinline__ void mma_bf(float* c, const unsigned* a, unsigned b0, unsigned b1) {
    asm volatile("mma.sync.aligned.m16n8k16.row.col.f32.bf16.bf16.f32 "
                 "{%0,%1,%2,%3}, {%4,%5,%6,%7}, {%8,%9}, {%0,%1,%2,%3};"
                 : "+f"(c[0]), "+f"(c[1]), "+f"(c[2]), "+f"(c[3])
                 : "r"(a[0]), "r"(a[1]), "r"(a[2]), "r"(a[3]), "r"(b0), "r"(b1));
}
// direct tile: [row128][kd32] bf16, stride 80B. trans tile: [kd32][col128] bf16, stride 272B.
__device__ __forceinline__ void ldA_dir(unsigned* a, unsigned tb, int mb, int ks, int L) {
    int q = L >> 3, rs = L & 7;
    ldsm4(a, tb + (unsigned)((mb + (q & 1) * 8 + rs) * 80 + (ks * 2 + (q >> 1)) * 16));
}
__device__ __forceinline__ void ldA_trn(unsigned* a, unsigned tb, int mb, int ks, int L) {
    int q = L >> 3, rs = L & 7;
    ldsm4t(a, tb + (unsigned)((ks * 16 + (q >> 1) * 8 + rs) * 272 + (mb + (q & 1) * 8) * 2));
}
__device__ __forceinline__ void ldB_dir(unsigned* b, unsigned tb, int nb, int ks, int L) {
    int q = L >> 3, rs = L & 7;
    ldsm4(b, tb + (unsigned)((nb + (q >> 1) * 8 + rs) * 80 + (ks * 2 + (q & 1)) * 16));
}
__device__ __forceinline__ void ldB_trn(unsigned* b, unsigned tb, int nb, int ks, int L) {
    int q = L >> 3, rs = L & 7;
    ldsm4t(b, tb + (unsigned)((ks * 16 + (q & 1) * 8 + rs) * 272 + (nb + (q >> 1) * 8) * 2));
}
__device__ __forceinline__ void split_pack(float a0, float a1, unsigned& hi, unsigned& lo) {
    __nv_bfloat162 h, l;
    h.x = __float2bfloat16_rn(a0); h.y = __float2bfloat16_rn(a1);
    l.x = __float2bfloat16_rn(a0 - __bfloat162float(h.x));
    l.y = __float2bfloat16_rn(a1 - __bfloat162float(h.y));
    hi = *(unsigned*)&h; lo = *(unsigned*)&l;
}
__device__ __forceinline__ unsigned pack_hi(float a0, float a1) {
    __nv_bfloat162 h;
    h.x = __float2bfloat16_rn(a0); h.y = __float2bfloat16_rn(a1);
    return *(unsigned*)&h;
}

// 3-product split chunk (separate hi/lo tiles), kd=32
template<int AT, int BT>
__device__ __forceinline__ void gemm_chunk(float (*acc)[4][4], unsigned ah, unsigned al,
                                           unsigned bh, unsigned bl, int wm, int wn, int L)
{
    #pragma unroll
    for (int ks = 0; ks < 2; ks++) {
        unsigned aH[16], aL[16], bH[8], bL[8];
        #pragma unroll
        for (int fm = 0; fm < 4; fm++) {
            int mb = wm * 64 + fm * 16;
            if (AT) { ldA_trn(aH + fm*4, ah, mb, ks, L); ldA_trn(aL + fm*4, al, mb, ks, L); }
            else    { ldA_dir(aH + fm*4, ah, mb, ks, L); ldA_dir(aL + fm*4, al, mb, ks, L); }
        }
        #pragma unroll
        for (int fp = 0; fp < 2; fp++) {
            int nb = wn * 32 + fp * 16;
            if (BT) { ldB_trn(bH + fp*4, bh, nb, ks, L); ldB_trn(bL + fp*4, bl, nb, ks, L); }
            else    { ldB_dir(bH + fp*4, bh, nb, ks, L); ldB_dir(bL + fp*4, bl, nb, ks, L); }
        }
        #pragma unroll
        for (int fm = 0; fm < 4; fm++)
            #pragma unroll
            for (int fn = 0; fn < 4; fn++) {
                int bi = (fn >> 1) * 4 + (fn & 1) * 2;
                mma_bf(acc[fm][fn], aH + fm*4, bH[bi], bH[bi+1]);
                mma_bf(acc[fm][fn], aH + fm*4, bL[bi], bL[bi+1]);
                mma_bf(acc[fm][fn], aL + fm*4, bH[bi], bH[bi+1]);
            }
    }
}

// 1-product pure bf16 chunk (both operands trans layout), kd=32
__device__ __forceinline__ void gemm_chunk1tt(float (*acc)[4][4], unsigned ah,
                                              unsigned bh, int wm, int wn, int L)
{
    #pragma unroll
    for (int ks = 0; ks < 2; ks++) {
        unsigned aH[16], bH[8];
        #pragma unroll
        for (int fm = 0; fm < 4; fm++)
            ldA_trn(aH + fm*4, ah, wm * 64 + fm * 16, ks, L);
        #pragma unroll
        for (int fp = 0; fp < 2; fp++)
            ldB_trn(bH + fp*4, bh, wn * 32 + fp * 16, ks, L);
        #pragma unroll
        for (int fm = 0; fm < 4; fm++)
            #pragma unroll
            for (int fn = 0; fn < 4; fn++) {
                int bi = (fn >> 1) * 4 + (fn & 1) * 2;
                mma_bf(acc[fm][fn], aH + fm*4, bH[bi], bH[bi+1]);
            }
    }
}

// ============ vprep: split x into padded bf16 hi/lo [b][c][XP_] ============
__global__ __launch_bounds__(256)
void vprep(const float* __restrict__ x)
{
    int row = blockIdx.x;                 // b*C + c
    size_t xb = (size_t)row * N_, ob = (size_t)row * XP_;
    for (int m = threadIdx.x; m < XP_; m += 256) {
        float v = (m < N_) ? __ldg(x + xb + m) : 0.f;
        __nv_bfloat16 h = __float2bfloat16_rn(v);
        g_Xhi[ob + m] = h;
        g_Xlo[ob + m] = __float2bfloat16_rn(v - __bfloat162float(h));
    }
}

// ============ proj: D[k,n] = W@x + b (3-product), store bf16 hi [b][k][n-pad] ============
__global__ __launch_bounds__(256, 2)
void proj_t(const float* __restrict__ Wq, const float* __restrict__ bq,
            const float* __restrict__ Wk, const float* __restrict__ bk)
{
    __shared__ __align__(16) char sm[20480 + 17408];
    unsigned sA = s2u(sm), sAl = sA + 10240, sB = sA + 20480, sBl = sB + 8704;
    int t = threadIdx.x, L = t & 31, w = t >> 5, wm = w & 1, wn = w >> 1;
    int z = blockIdx.z, b = z >> 1, isK = z & 1;
    const float* W    = isK ? Wk : Wq;
    const float* bias = isK ? bk : bq;
    __nv_bfloat16* Ohi = isK ? g_Khi : g_Qhi;
    int n0 = blockIdx.x * 128, k0 = blockIdx.y * 128;
    const __nv_bfloat16* Xh = g_Xhi + (size_t)b * C_ * XP_;
    const __nv_bfloat16* Xl = g_Xlo + (size_t)b * C_ * XP_;

    float acc[4][4][4] = {};
    for (int c0 = 0; c0 < C_; c0 += 32) {
        {   // A = W rows k (coalesced float4, split in-loop; W is small)
            int r = t >> 1, hf = t & 1;
            const float4* Wp = (const float4*)(W + (size_t)(k0 + r) * C_ + c0 + hf * 16);
            unsigned hi[8], lo[8];
            #pragma unroll
            for (int v = 0; v < 4; v++) {
                float4 f = Wp[v];
                split_pack(f.x, f.y, hi[2*v], lo[2*v]);
                split_pack(f.z, f.w, hi[2*v+1], lo[2*v+1]);
            }
            unsigned off = r * 80 + hf * 32;
            *(uint4*)(sm + off)              = ((uint4*)hi)[0];
            *(uint4*)(sm + off + 16)         = ((uint4*)hi)[1];
            *(uint4*)(sm + 10240 + off)      = ((uint4*)lo)[0];
            *(uint4*)(sm + 10240 + off + 16) = ((uint4*)lo)[1];
        }
        {   // B = x rows c, trans layout — pure uint4 copies from pre-split
            int r = t >> 3, seg = t & 7;
            size_t src = (size_t)(c0 + r) * XP_ + n0 + seg * 16;
            unsigned off = 20480 + r * 272 + seg * 32;
            *(uint4*)(sm + off)             = *(const uint4*)(Xh + src);
            *(uint4*)(sm + off + 16)        = *(const uint4*)(Xh + src + 8);
            *(uint4*)(sm + 8704 + off)      = *(const uint4*)(Xl + src);
            *(uint4*)(sm + 8704 + off + 16) = *(const uint4*)(Xl + src + 8);
        }
        __syncthreads();
        gemm_chunk<0, 1>(acc, sA, sAl, sB, sBl, wm, wn, L);
        __syncthreads();
    }
    #pragma unroll
    for (int fm = 0; fm < 4; fm++) {
        #pragma unroll
        for (int rh = 0; rh < 2; rh++) {
            int k = k0 + wm * 64 + fm * 16 + (L >> 2) + rh * 8;
            float bia = bias[k];
            #pragma unroll
            for (int fn = 0; fn < 4; fn++) {
                int n = n0 + wn * 32 + fn * 8 + 2 * (L & 3);
                unsigned hp = pack_hi(acc[fm][fn][rh*2] + bia, acc[fm][fn][rh*2+1] + bia);
                *(unsigned*)(Ohi + ((size_t)b * CK_ + k) * MPQ_ + n) = hp;
            }
        }
    }
}

// ============ sim: S[n,m] = (Q.K^T)*scale*fg + row stats (pure bf16 MMA) ============
__global__ __launch_bounds__(256, 2)
void sim_t(const float* __restrict__ fg)
{
    __shared__ __align__(16) char sm[17408 + 6144];
    unsigned sQ = s2u(sm), sK = sQ + 8704;
    float* red = (float*)(sm + 17408);     // [3][8][64]
    int t = threadIdx.x, L = t & 31, w = t >> 5, wm = w & 1, wn = w >> 1;
    int b = blockIdx.z, m0 = blockIdx.x * 128, n0 = blockIdx.y * 128;

    float acc[4][4][4] = {};
    for (int k0 = 0; k0 < CK_; k0 += 32) {
        // same mapping as R6/R9 fill, hi arrays only
        int r = t >> 3, seg = t & 7;
        size_t qi = ((size_t)b * CK_ + k0 + r) * MPQ_ + n0 + seg * 16;
        size_t ki = ((size_t)b * CK_ + k0 + r) * MPQ_ + m0 + seg * 16;
        unsigned off = r * 272 + seg * 32;
        *(uint4*)(sm + off)             = *(const uint4*)(g_Qhi + qi);
        *(uint4*)(sm + off + 16)        = *(const uint4*)(g_Qhi + qi + 8);
        *(uint4*)(sm + 8704 + off)      = *(const uint4*)(g_Khi + ki);
        *(uint4*)(sm + 8704 + off + 16) = *(const uint4*)(g_Khi + ki + 8);
        __syncthreads();
        gemm_chunk1tt(acc, sQ, sK, wm, wn, L);
        __syncthreads();
    }

    float rmn[4][2], rss[4][2], rfs[4][2];
    #pragma unroll
    for (int fm = 0; fm < 4; fm++)
        #pragma unroll
        for (int rh = 0; rh < 2; rh++) { rmn[fm][rh] = 3.4e38f; rss[fm][rh] = 0.f; rfs[fm][rh] = 0.f; }

    #pragma unroll
    for (int fm = 0; fm < 4; fm++)
        #pragma unroll
        for (int rh = 0; rh < 2; rh++) {
            int n = n0 + wm * 64 + fm * 16 + (L >> 2) + rh * 8;
            if (n < N_) {
                size_t fb = (size_t)b * N_ * N_ + (size_t)n * N_;
                size_t sbv = (size_t)b * N_ * MP2_ + (size_t)n * MP2_;
                #pragma unroll
                for (int fn = 0; fn < 4; fn++)
                    #pragma unroll
                    for (int e = 0; e < 2; e++) {
                        int m = m0 + wn * 32 + fn * 8 + 2 * (L & 3) + e;
                        if (m < N_) {
                            float f = __ldg(fg + fb + m);
                            float s1 = acc[fm][fn][rh*2 + e] * SCALE_ * f;
                            g_S[sbv + m] = s1;
                            rmn[fm][rh] = fminf(rmn[fm][rh], s1);
                            rss[fm][rh] += s1 * f;
                            rfs[fm][rh] += f;
                        }
                    }
            }
        }
    #pragma unroll
    for (int fm = 0; fm < 4; fm++)
        #pragma unroll
        for (int rh = 0; rh < 2; rh++) {
            #pragma unroll
            for (int xr = 1; xr < 4; xr <<= 1) {
                rmn[fm][rh] = fminf(rmn[fm][rh], __shfl_xor_sync(0xFFFFFFFFu, rmn[fm][rh], xr));
                rss[fm][rh] += __shfl_xor_sync(0xFFFFFFFFu, rss[fm][rh], xr);
                rfs[fm][rh] += __shfl_xor_sync(0xFFFFFFFFu, rfs[fm][rh], xr);
            }
            if ((L & 3) == 0) {
                int ri = w * 64 + fm * 16 + rh * 8 + (L >> 2);
                red[ri] = rmn[fm][rh];
                red[512 + ri] = rss[fm][rh];
                red[1024 + ri] = rfs[fm][rh];
            }
        }
    __syncthreads();
    if (t < 128) {
        int hf = t >> 6, row = t & 63;
        float mn = 3.4e38f, ss = 0.f, fs = 0.f;
        #pragma unroll
        for (int j = 0; j < 4; j++) {
            int ww = hf + 2 * j;
            mn = fminf(mn, red[ww * 64 + row]);
            ss += red[512 + ww * 64 + row];
            fs += red[1024 + ww * 64 + row];
        }
        int n = n0 + hf * 64 + row;
        if (n < N_) {
            size_t idx = ((size_t)b * NTT_ + blockIdx.x) * N_ + n;
            g_pmin[idx] = mn; g_pss[idx] = ss; g_pfs[idx] = fs;
        }
    }
}

// ============ xform: finalize stats + attn = (S-min)*fg*inv + bg, split bf16 ============
__global__ __launch_bounds__(256)
void xform(const float* __restrict__ fg, const float* __restrict__ bg)
{
    __shared__ float s_mn, s_iv;
    int r = blockIdx.x;               // b*N_ + n
    int t = threadIdx.x;
    int b = r / N_, n = r - b * N_;
    if (t < 32) {
        float mn = 3.4e38f, ss = 0.f, fs = 0.f;
        if (t < NTT_) {
            size_t idx = ((size_t)b * NTT_ + t) * N_ + n;
            mn = g_pmin[idx]; ss = g_pss[idx]; fs = g_pfs[idx];
        }
        #pragma unroll
        for (int xr = 16; xr > 0; xr >>= 1) {
            mn = fminf(mn, __shfl_xor_sync(0xFFFFFFFFu, mn, xr));
            ss += __shfl_xor_sync(0xFFFFFFFFu, ss, xr);
            fs += __shfl_xor_sync(0xFFFFFFFFu, fs, xr);
        }
        if (t == 0) { s_mn = mn; s_iv = 1.f / ((ss - mn * fs) + EPS_); }
    }
    __syncthreads();
    float mn = s_mn, iv = s_iv;
    size_t sbase = (size_t)r * MP2_;
    size_t gbase = (size_t)r * N_;
    for (int m = t; m < MP2_; m += 256) {
        float a = 0.f;
        if (m < N_) {
            float s1 = g_S[sbase + m];
            float f  = __ldg(fg + gbase + m);
            float g  = __ldg(bg + gbase + m);
            a = (s1 - mn) * f * iv + g;
        }
        __nv_bfloat16 h = __float2bfloat16_rn(a);
        g_AHi[sbase + m] = h;
        g_ALo[sbase + m] = __float2bfloat16_rn(a - __bfloat162float(h));
    }
}

// ============ ctx: out[c,n] = gamma*(attn @ x^T)[n,c] + x[c,n] (3-product) ============
__global__ __launch_bounds__(256, 2)
void ctx_t(const float* __restrict__ x, const float* __restrict__ gamma,
           float* __restrict__ out)
{
    __shared__ __align__(16) char sm[40960];
    unsigned sA = s2u(sm), sAl = sA + 10240, sB = sA + 20480, sBl = sA + 30720;
    int t = threadIdx.x, L = t & 31, w = t >> 5, wm = w & 1, wn = w >> 1;
    int b = blockIdx.z, n0 = blockIdx.x * 128, c0 = blockIdx.y * 128;
    const __nv_bfloat16* Xh = g_Xhi + (size_t)b * C_ * XP_;
    const __nv_bfloat16* Xl = g_Xlo + (size_t)b * C_ * XP_;

    float acc[4][4][4] = {};
    for (int m0 = 0; m0 < MP2_; m0 += 32) {
        int r = t >> 1, hf = t & 1;
        {   // A = attn rows n (uint4, zero-pad n>=N rows)
            int n = n0 + r;
            unsigned off = r * 80 + hf * 32;
            if (n < N_) {
                size_t ai = ((size_t)b * N_ + n) * MP2_ + m0 + hf * 16;
                *(uint4*)(sm + off)              = *(const uint4*)(g_AHi + ai);
                *(uint4*)(sm + off + 16)         = *(const uint4*)(g_AHi + ai + 8);
                *(uint4*)(sm + 10240 + off)      = *(const uint4*)(g_ALo + ai);
                *(uint4*)(sm + 10240 + off + 16) = *(const uint4*)(g_ALo + ai + 8);
            } else {
                uint4 z = make_uint4(0, 0, 0, 0);
                *(uint4*)(sm + off) = z; *(uint4*)(sm + off + 16) = z;
                *(uint4*)(sm + 10240 + off) = z; *(uint4*)(sm + 10240 + off + 16) = z;
            }
        }
        {   // B = x rows c — pure uint4 copies from pre-split
            size_t src = (size_t)(c0 + r) * XP_ + m0 + hf * 16;
            unsigned off = 20480 + r * 80 + hf * 32;
            *(uint4*)(sm + off)              = *(const uint4*)(Xh + src);
            *(uint4*)(sm + off + 16)         = *(const uint4*)(Xh + src + 8);
            *(uint4*)(sm + 10240 + off)      = *(const uint4*)(Xl + src);
            *(uint4*)(sm + 10240 + off + 16) = *(const uint4*)(Xl + src + 8);
        }
        __syncthreads();
        gemm_chunk<0, 0>(acc, sA, sAl, sB, sBl, wm, wn, L);
        __syncthreads();
    }

    float gam = __ldg(gamma);
    float* stage = (float*)sm;
    #pragma unroll 1
    for (int ch = 0; ch < 2; ch++) {
        if ((wn >> 1) == ch) {
            #pragma unroll
            for (int fm = 0; fm < 4; fm++)
                #pragma unroll
                for (int fn = 0; fn < 4; fn++)
                    #pragma unroll
                    for (int e = 0; e < 4; e++) {
                        int cl = (wn & 1) * 32 + fn * 8 + 2 * (L & 3) + (e & 1);
                        int nl = wm * 64 + fm * 16 + (L >> 2) + (e >> 1) * 8;
                        stage[cl * 132 + nl] = acc[fm][fn][e];
                    }
        }
        __syncthreads();
        #pragma unroll 1
        for (int rr = 0; rr < 8; rr++) {
            int cc = w * 8 + rr;
            int c = c0 + ch * 64 + cc;
            size_t ob = ((size_t)b * C_ + c) * N_;
            #pragma unroll
            for (int jj = 0; jj < 4; jj++) {
                int n = n0 + jj * 32 + L;
                if (n < N_)
                    out[ob + n] = gam * stage[cc * 132 + jj * 32 + L] + __ldg(x + ob + n);
            }
        }
        __syncthreads();
    }
}

// ============================================================
extern "C" void kernel_launch(void* const* d_in, const int* in_sizes, int n_in,
                              void* d_out, int out_size)
{
    const float* x     = (const float*)d_in[0];
    const float* fg    = (const float*)d_in[1];
    const float* bg    = (const float*)d_in[2];
    const float* Wq    = (const float*)d_in[3];
    const float* bq    = (const float*)d_in[4];
    const float* Wk    = (const float*)d_in[5];
    const float* bk    = (const float*)d_in[6];
    const float* gamma = (const float*)d_in[7];
    float* out = (float*)d_out;

    vprep<<<B_ * C_, 256>>>(x);
    proj_t<<<dim3(14, 2, 32), 256>>>(Wq, bq, Wk, bk);
    sim_t<<<dim3(14, 14, 16), 256>>>(fg);
    xform<<<B_ * N_, 256>>>(fg, bg);
    ctx_t<<<dim3(14, 4, 16), 256>>>(x, gamma, out);
}

// round 12
// speedup vs baseline: 1.4510x; 1.0440x over previous
#include <cuda_runtime.h>
#include <cuda_bf16.h>

#define B_    16
#define C_    512
#define N_    1681
#define CK_   256
#define MPQ_  1792          // Q/K n-padding (14*128)
#define MP2_  1728          // attention m-padding (54*32)
#define XP_   1792          // x-split padding
#define NTT_  14
#define SCALE_ 0.0625f
#define EPS_  1e-5f

// ---------------- device scratch ----------------
__device__ __nv_bfloat16 g_Qhi[(size_t)B_*CK_*MPQ_];
__device__ __nv_bfloat16 g_Khi[(size_t)B_*CK_*MPQ_];
__device__ __nv_bfloat16 g_Xhi[(size_t)B_*C_*XP_],  g_Xlo[(size_t)B_*C_*XP_];
__device__ __nv_bfloat16 g_Sb[(size_t)B_*N_*MP2_];
__device__ __nv_bfloat16 g_AHi[(size_t)B_*N_*MP2_], g_ALo[(size_t)B_*N_*MP2_];
__device__ float g_pmin[B_*NTT_*N_], g_pss[B_*NTT_*N_], g_pfs[B_*NTT_*N_];

// ---------------- helpers ----------------
__device__ __forceinline__ unsigned s2u(const void* p) {
    unsigned a;
    asm("{ .reg .u64 t; cvta.to.shared.u64 t, %1; cvt.u32.u64 %0, t; }" : "=r"(a) : "l"(p));
    return a;
}
__device__ __forceinline__ void ldsm4(unsigned* r, unsigned a) {
    asm volatile("ldmatrix.sync.aligned.m8n8.x4.shared.b16 {%0,%1,%2,%3}, [%4];"
                 : "=r"(r[0]), "=r"(r[1]), "=r"(r[2]), "=r"(r[3]) : "r"(a));
}
__device__ __forceinline__ void ldsm4t(unsigned* r, unsigned a) {
    asm volatile("ldmatrix.sync.aligned.m8n8.x4.trans.shared.b16 {%0,%1,%2,%3}, [%4];"
                 : "=r"(r[0]), "=r"(r[1]), "=r"(r[2]), "=r"(r[3]) : "r"(a));
}
__device__ __forceinline__ void mma_bf(float* c, const unsigned* a, unsigned b0, unsigned b1) {
    asm volatile("mma.sync.aligned.m16n8k16.row.col.f32.bf16.bf16.f32 "
                 "{%0,%1,%2,%3}, {%4,%5,%6,%7}, {%8,%9}, {%0,%1,%2,%3};"
                 : "+f"(c[0]), "+f"(c[1]), "+f"(c[2]), "+f"(c[3])
                 : "r"(a[0]), "r"(a[1]), "r"(a[2]), "r"(a[3]), "r"(b0), "r"(b1));
}
// direct tile: [row128][kd32] bf16, stride 80B. trans tile: [kd32][col128] bf16, stride 272B.
__device__ __forceinline__ void ldA_dir(unsigned* a, unsigned tb, int mb, int ks, int L) {
    int q = L >> 3, rs = L & 7;
    ldsm4(a, tb + (unsigned)((mb + (q & 1) * 8 + rs) * 80 + (ks * 2 + (q >> 1)) * 16));
}
__device__ __forceinline__ void ldA_trn(unsigned* a, unsigned tb, int mb, int ks, int L) {
    int q = L >> 3, rs = L & 7;
    ldsm4t(a, tb + (unsigned)((ks * 16 + (q >> 1) * 8 + rs) * 272 + (mb + (q & 1) * 8) * 2));
}
__device__ __forceinline__ void ldB_dir(unsigned* b, unsigned tb, int nb, int ks, int L) {
    int q = L >> 3, rs = L & 7;
    ldsm4(b, tb + (unsigned)((nb + (q >> 1) * 8 + rs) * 80 + (ks * 2 + (q & 1)) * 16));
}
__device__ __forceinline__ void ldB_trn(unsigned* b, unsigned tb, int nb, int ks, int L) {
    int q = L >> 3, rs = L & 7;
    ldsm4t(b, tb + (unsigned)((ks * 16 + (q & 1) * 8 + rs) * 272 + (nb + (q >> 1) * 8) * 2));
}
__device__ __forceinline__ void split_pack(float a0, float a1, unsigned& hi, unsigned& lo) {
    __nv_bfloat162 h, l;
    h.x = __float2bfloat16_rn(a0); h.y = __float2bfloat16_rn(a1);
    l.x = __float2bfloat16_rn(a0 - __bfloat162float(h.x));
    l.y = __float2bfloat16_rn(a1 - __bfloat162float(h.y));
    hi = *(unsigned*)&h; lo = *(unsigned*)&l;
}
__device__ __forceinline__ unsigned pack_hi(float a0, float a1) {
    __nv_bfloat162 h;
    h.x = __float2bfloat16_rn(a0); h.y = __float2bfloat16_rn(a1);
    return *(unsigned*)&h;
}

// 3-product split chunk (separate hi/lo tiles), kd=32
template<int AT, int BT>
__device__ __forceinline__ void gemm_chunk(float (*acc)[4][4], unsigned ah, unsigned al,
                                           unsigned bh, unsigned bl, int wm, int wn, int L)
{
    #pragma unroll
    for (int ks = 0; ks < 2; ks++) {
        unsigned aH[16], aL[16], bH[8], bL[8];
        #pragma unroll
        for (int fm = 0; fm < 4; fm++) {
            int mb = wm * 64 + fm * 16;
            if (AT) { ldA_trn(aH + fm*4, ah, mb, ks, L); ldA_trn(aL + fm*4, al, mb, ks, L); }
            else    { ldA_dir(aH + fm*4, ah, mb, ks, L); ldA_dir(aL + fm*4, al, mb, ks, L); }
        }
        #pragma unroll
        for (int fp = 0; fp < 2; fp++) {
            int nb = wn * 32 + fp * 16;
            if (BT) { ldB_trn(bH + fp*4, bh, nb, ks, L); ldB_trn(bL + fp*4, bl, nb, ks, L); }
            else    { ldB_dir(bH + fp*4, bh, nb, ks, L); ldB_dir(bL + fp*4, bl, nb, ks, L); }
        }
        #pragma unroll
        for (int fm = 0; fm < 4; fm++)
            #pragma unroll
            for (int fn = 0; fn < 4; fn++) {
                int bi = (fn >> 1) * 4 + (fn & 1) * 2;
                mma_bf(acc[fm][fn], aH + fm*4, bH[bi], bH[bi+1]);
                mma_bf(acc[fm][fn], aH + fm*4, bL[bi], bL[bi+1]);
                mma_bf(acc[fm][fn], aL + fm*4, bH[bi], bH[bi+1]);
            }
    }
}

// 1-product pure bf16 chunk (both operands trans layout), kd=32
__device__ __forceinline__ void gemm_chunk1tt(float (*acc)[4][4], unsigned ah,
                                              unsigned bh, int wm, int wn, int L)
{
    #pragma unroll
    for (int ks = 0; ks < 2; ks++) {
        unsigned aH[16], bH[8];
        #pragma unroll
        for (int fm = 0; fm < 4; fm++)
            ldA_trn(aH + fm*4, ah, wm * 64 + fm * 16, ks, L);
        #pragma unroll
        for (int fp = 0; fp < 2; fp++)
            ldB_trn(bH + fp*4, bh, wn * 32 + fp * 16, ks, L);
        #pragma unroll
        for (int fm = 0; fm < 4; fm++)
            #pragma unroll
            for (int fn = 0; fn < 4; fn++) {
                int bi = (fn >> 1) * 4 + (fn & 1) * 2;
                mma_bf(acc[fm][fn], aH + fm*4, bH[bi], bH[bi+1]);
            }
    }
}

// ============ vprep: split x into padded bf16 hi/lo [b][c][XP_] ============
__global__ __launch_bounds__(256)
void vprep(const float* __restrict__ x)
{
    int row = blockIdx.x;                 // b*C + c
    size_t xb = (size_t)row * N_, ob = (size_t)row * XP_;
    for (int m = threadIdx.x; m < XP_; m += 256) {
        float v = (m < N_) ? __ldg(x + xb + m) : 0.f;
        __nv_bfloat16 h = __float2bfloat16_rn(v);
        g_Xhi[ob + m] = h;
        g_Xlo[ob + m] = __float2bfloat16_rn(v - __bfloat162float(h));
    }
}

// ============ proj: D[k,n] = W@x + b (3-product), store bf16 hi [b][k][n-pad] ============
__global__ __launch_bounds__(256, 2)
void proj_t(const float* __restrict__ Wq, const float* __restrict__ bq,
            const float* __restrict__ Wk, const float* __restrict__ bk)
{
    __shared__ __align__(16) char sm[20480 + 17408];
    unsigned sA = s2u(sm), sAl = sA + 10240, sB = sA + 20480, sBl = sB + 8704;
    int t = threadIdx.x, L = t & 31, w = t >> 5, wm = w & 1, wn = w >> 1;
    int z = blockIdx.z, b = z >> 1, isK = z & 1;
    const float* W    = isK ? Wk : Wq;
    const float* bias = isK ? bk : bq;
    __nv_bfloat16* Ohi = isK ? g_Khi : g_Qhi;
    int n0 = blockIdx.x * 128, k0 = blockIdx.y * 128;
    const __nv_bfloat16* Xh = g_Xhi + (size_t)b * C_ * XP_;
    const __nv_bfloat16* Xl = g_Xlo + (size_t)b * C_ * XP_;

    float acc[4][4][4] = {};
    for (int c0 = 0; c0 < C_; c0 += 32) {
        {   // A = W rows k
            int r = t >> 1, hf = t & 1;
            const float4* Wp = (const float4*)(W + (size_t)(k0 + r) * C_ + c0 + hf * 16);
            unsigned hi[8], lo[8];
            #pragma unroll
            for (int v = 0; v < 4; v++) {
                float4 f = Wp[v];
                split_pack(f.x, f.y, hi[2*v], lo[2*v]);
                split_pack(f.z, f.w, hi[2*v+1], lo[2*v+1]);
            }
            unsigned off = r * 80 + hf * 32;
            *(uint4*)(sm + off)              = ((uint4*)hi)[0];
            *(uint4*)(sm + off + 16)         = ((uint4*)hi)[1];
            *(uint4*)(sm + 10240 + off)      = ((uint4*)lo)[0];
            *(uint4*)(sm + 10240 + off + 16) = ((uint4*)lo)[1];
        }
        {   // B = x rows c, trans layout — pure uint4 copies from pre-split
            int r = t >> 3, seg = t & 7;
            size_t src = (size_t)(c0 + r) * XP_ + n0 + seg * 16;
            unsigned off = 20480 + r * 272 + seg * 32;
            *(uint4*)(sm + off)             = *(const uint4*)(Xh + src);
            *(uint4*)(sm + off + 16)        = *(const uint4*)(Xh + src + 8);
            *(uint4*)(sm + 8704 + off)      = *(const uint4*)(Xl + src);
            *(uint4*)(sm + 8704 + off + 16) = *(const uint4*)(Xl + src + 8);
        }
        __syncthreads();
        gemm_chunk<0, 1>(acc, sA, sAl, sB, sBl, wm, wn, L);
        __syncthreads();
    }
    #pragma unroll
    for (int fm = 0; fm < 4; fm++) {
        #pragma unroll
        for (int rh = 0; rh < 2; rh++) {
            int k = k0 + wm * 64 + fm * 16 + (L >> 2) + rh * 8;
            float bia = bias[k];
            #pragma unroll
            for (int fn = 0; fn < 4; fn++) {
                int n = n0 + wn * 32 + fn * 8 + 2 * (L & 3);
                unsigned hp = pack_hi(acc[fm][fn][rh*2] + bia, acc[fm][fn][rh*2+1] + bia);
                *(unsigned*)(Ohi + ((size_t)b * CK_ + k) * MPQ_ + n) = hp;
            }
        }
    }
}

// ============ sim: Sb[n,m] = bf16((Q.K^T)*scale*fg) + row stats (pure bf16 MMA) ============
__global__ __launch_bounds__(256, 2)
void sim_t(const float* __restrict__ fg)
{
    __shared__ __align__(16) char sm[17408 + 6144];
    unsigned sQ = s2u(sm), sK = sQ + 8704;
    float* red = (float*)(sm + 17408);     // [3][8][64]
    int t = threadIdx.x, L = t & 31, w = t >> 5, wm = w & 1, wn = w >> 1;
    int b = blockIdx.z, m0 = blockIdx.x * 128, n0 = blockIdx.y * 128;

    float acc[4][4][4] = {};
    for (int k0 = 0; k0 < CK_; k0 += 32) {
        int r = t >> 3, seg = t & 7;
        size_t qi = ((size_t)b * CK_ + k0 + r) * MPQ_ + n0 + seg * 16;
        size_t ki = ((size_t)b * CK_ + k0 + r) * MPQ_ + m0 + seg * 16;
        unsigned off = r * 272 + seg * 32;
        *(uint4*)(sm + off)             = *(const uint4*)(g_Qhi + qi);
        *(uint4*)(sm + off + 16)        = *(const uint4*)(g_Qhi + qi + 8);
        *(uint4*)(sm + 8704 + off)      = *(const uint4*)(g_Khi + ki);
        *(uint4*)(sm + 8704 + off + 16) = *(const uint4*)(g_Khi + ki + 8);
        __syncthreads();
        gemm_chunk1tt(acc, sQ, sK, wm, wn, L);
        __syncthreads();
    }

    float rmn[4][2], rss[4][2], rfs[4][2];
    #pragma unroll
    for (int fm = 0; fm < 4; fm++)
        #pragma unroll
        for (int rh = 0; rh < 2; rh++) { rmn[fm][rh] = 3.4e38f; rss[fm][rh] = 0.f; rfs[fm][rh] = 0.f; }

    #pragma unroll
    for (int fm = 0; fm < 4; fm++)
        #pragma unroll
        for (int rh = 0; rh < 2; rh++) {
            int n = n0 + wm * 64 + fm * 16 + (L >> 2) + rh * 8;
            if (n < N_) {
                size_t fb = (size_t)b * N_ * N_ + (size_t)n * N_;
                size_t sbv = (size_t)b * N_ * MP2_ + (size_t)n * MP2_;
                #pragma unroll
                for (int fn = 0; fn < 4; fn++) {
                    int m = m0 + wn * 32 + fn * 8 + 2 * (L & 3);
                    float s0 = 0.f, s1v = 0.f;
                    if (m < N_) {
                        float f = __ldg(fg + fb + m);
                        s0 = acc[fm][fn][rh*2] * SCALE_ * f;
                        rmn[fm][rh] = fminf(rmn[fm][rh], s0);
                        rss[fm][rh] += s0 * f;
                        rfs[fm][rh] += f;
                    }
                    if (m + 1 < N_) {
                        float f = __ldg(fg + fb + m + 1);
                        s1v = acc[fm][fn][rh*2+1] * SCALE_ * f;
                        rmn[fm][rh] = fminf(rmn[fm][rh], s1v);
                        rss[fm][rh] += s1v * f;
                        rfs[fm][rh] += f;
                    }
                    if (m < N_)
                        *(unsigned*)(g_Sb + sbv + m) = pack_hi(s0, s1v);
                }
            }
        }
    #pragma unroll
    for (int fm = 0; fm < 4; fm++)
        #pragma unroll
        for (int rh = 0; rh < 2; rh++) {
            #pragma unroll
            for (int xr = 1; xr < 4; xr <<= 1) {
                rmn[fm][rh] = fminf(rmn[fm][rh], __shfl_xor_sync(0xFFFFFFFFu, rmn[fm][rh], xr));
                rss[fm][rh] += __shfl_xor_sync(0xFFFFFFFFu, rss[fm][rh], xr);
                rfs[fm][rh] += __shfl_xor_sync(0xFFFFFFFFu, rfs[fm][rh], xr);
            }
            if ((L & 3) == 0) {
                int ri = w * 64 + fm * 16 + rh * 8 + (L >> 2);
                red[ri] = rmn[fm][rh];
                red[512 + ri] = rss[fm][rh];
                red[1024 + ri] = rfs[fm][rh];
            }
        }
    __syncthreads();
    if (t < 128) {
        int hf = t >> 6, row = t & 63;
        float mn = 3.4e38f, ss = 0.f, fs = 0.f;
        #pragma unroll
        for (int j = 0; j < 4; j++) {
            int ww = hf + 2 * j;
            mn = fminf(mn, red[ww * 64 + row]);
            ss += red[512 + ww * 64 + row];
            fs += red[1024 + ww * 64 + row];
        }
        int n = n0 + hf * 64 + row;
        if (n < N_) {
            size_t idx = ((size_t)b * NTT_ + blockIdx.x) * N_ + n;
            g_pmin[idx] = mn; g_pss[idx] = ss; g_pfs[idx] = fs;
        }
    }
}

// ============ xform: finalize stats + attn = (Sb-min)*fg*inv + bg, split bf16 ============
// Sb/AHi/ALo accesses vectorized (aligned, padded stride); fg/bg scalar (unaligned rows)
__global__ __launch_bounds__(256)
void xform(const float* __restrict__ fg, const float* __restrict__ bg)
{
    __shared__ float s_mn, s_iv;
    int r = blockIdx.x;               // b*N_ + n
    int t = threadIdx.x;
    int b = r / N_, n = r - b * N_;
    if (t < 32) {
        float mn = 3.4e38f, ss = 0.f, fs = 0.f;
        if (t < NTT_) {
            size_t idx = ((size_t)b * NTT_ + t) * N_ + n;
            mn = g_pmin[idx]; ss = g_pss[idx]; fs = g_pfs[idx];
        }
        #pragma unroll
        for (int xr = 16; xr > 0; xr >>= 1) {
            mn = fminf(mn, __shfl_xor_sync(0xFFFFFFFFu, mn, xr));
            ss += __shfl_xor_sync(0xFFFFFFFFu, ss, xr);
            fs += __shfl_xor_sync(0xFFFFFFFFu, fs, xr);
        }
        if (t == 0) { s_mn = mn; s_iv = 1.f / ((ss - mn * fs) + EPS_); }
    }
    __syncthreads();
    float mn = s_mn, iv = s_iv;
    size_t sbase = (size_t)r * MP2_;
    size_t gbase = (size_t)r * N_;
    // groups of 4 m: 0..419 fully in-bounds, 420 mixed, 421..431 pure pad
    for (int g = t; g < MP2_ / 4; g += 256) {
        int m = g * 4;
        float a[4];
        if (g < 420) {
            uint2 sp = *(const uint2*)(g_Sb + sbase + m);
            __nv_bfloat162 s01 = *(__nv_bfloat162*)&sp.x;
            __nv_bfloat162 s23 = *(__nv_bfloat162*)&sp.y;
            float sv[4] = { __bfloat162float(s01.x), __bfloat162float(s01.y),
                            __bfloat162float(s23.x), __bfloat162float(s23.y) };
            #pragma unroll
            for (int e = 0; e < 4; e++)
                a[e] = (sv[e] - mn) * __ldg(fg + gbase + m + e) * iv + __ldg(bg + gbase + m + e);
        } else if (g == 420) {
            #pragma unroll
            for (int e = 0; e < 4; e++) {
                int mm = m + e;
                if (mm < N_) {
                    float s1 = __bfloat162float(g_Sb[sbase + mm]);
                    a[e] = (s1 - mn) * __ldg(fg + gbase + mm) * iv + __ldg(bg + gbase + mm);
                } else a[e] = 0.f;
            }
        } else {
            a[0] = a[1] = a[2] = a[3] = 0.f;
        }
        unsigned h01, l01, h23, l23;
        split_pack(a[0], a[1], h01, l01);
        split_pack(a[2], a[3], h23, l23);
        *(uint2*)(g_AHi + sbase + m) = make_uint2(h01, h23);
        *(uint2*)(g_ALo + sbase + m) = make_uint2(l01, l23);
    }
}

// ============ ctx: out[c,n] = gamma*(attn @ x^T)[n,c] + x[c,n] (3-product) ============
__global__ __launch_bounds__(256, 2)
void ctx_t(const float* __restrict__ x, const float* __restrict__ gamma,
           float* __restrict__ out)
{
    __shared__ __align__(16) char sm[40960];
    unsigned sA = s2u(sm), sAl = sA + 10240, sB = sA + 20480, sBl = sA + 30720;
    int t = threadIdx.x, L = t & 31, w = t >> 5, wm = w & 1, wn = w >> 1;
    int b = blockIdx.z, n0 = blockIdx.x * 128, c0 = blockIdx.y * 128;
    const __nv_bfloat16* Xh = g_Xhi + (size_t)b * C_ * XP_;
    const __nv_bfloat16* Xl = g_Xlo + (size_t)b * C_ * XP_;

    float acc[4][4][4] = {};
    for (int m0 = 0; m0 < MP2_; m0 += 32) {
        int r = t >> 1, hf = t & 1;
        {   // A = attn rows n (uint4, zero-pad n>=N rows)
            int n = n0 + r;
            unsigned off = r * 80 + hf * 32;
            if (n < N_) {
                size_t ai = ((size_t)b * N_ + n) * MP2_ + m0 + hf * 16;
                *(uint4*)(sm + off)              = *(const uint4*)(g_AHi + ai);
                *(uint4*)(sm + off + 16)         = *(const uint4*)(g_AHi + ai + 8);
                *(uint4*)(sm + 10240 + off)      = *(const uint4*)(g_ALo + ai);
                *(uint4*)(sm + 10240 + off + 16) = *(const uint4*)(g_ALo + ai + 8);
            } else {
                uint4 z = make_uint4(0, 0, 0, 0);
                *(uint4*)(sm + off) = z; *(uint4*)(sm + off + 16) = z;
                *(uint4*)(sm + 10240 + off) = z; *(uint4*)(sm + 10240 + off + 16) = z;
            }
        }
        {   // B = x rows c — pure uint4 copies from pre-split
            size_t src = (size_t)(c0 + r) * XP_ + m0 + hf * 16;
            unsigned off = 20480 + r * 80 + hf * 32;
            *(uint4*)(sm + off)              = *(const uint4*)(Xh + src);
            *(uint4*)(sm + off + 16)         = *(const uint4*)(Xh + src + 8);
            *(uint4*)(sm + 10240 + off)      = *(const uint4*)(Xl + src);
            *(uint4*)(sm + 10240 + off + 16) = *(const uint4*)(Xl + src + 8);
        }
        __syncthreads();
        gemm_chunk<0, 0>(acc, sA, sAl, sB, sBl, wm, wn, L);
        __syncthreads();
    }

    float gam = __ldg(gamma);
    float* stage = (float*)sm;
    #pragma unroll 1
    for (int ch = 0; ch < 2; ch++) {
        if ((wn >> 1) == ch) {
            #pragma unroll
            for (int fm = 0; fm < 4; fm++)
                #pragma unroll
                for (int fn = 0; fn < 4; fn++)
                    #pragma unroll
                    for (int e = 0; e < 4; e++) {
                        int cl = (wn & 1) * 32 + fn * 8 + 2 * (L & 3) + (e & 1);
                        int nl = wm * 64 + fm * 16 + (L >> 2) + (e >> 1) * 8;
                        stage[cl * 132 + nl] = acc[fm][fn][e];
                    }
        }
        __syncthreads();
        #pragma unroll 1
        for (int rr = 0; rr < 8; rr++) {
            int cc = w * 8 + rr;
            int c = c0 + ch * 64 + cc;
            size_t ob = ((size_t)b * C_ + c) * N_;
            #pragma unroll
            for (int jj = 0; jj < 4; jj++) {
                int n = n0 + jj * 32 + L;
                if (n < N_)
                    out[ob + n] = gam * stage[cc * 132 + jj * 32 + L] + __ldg(x + ob + n);
            }
        }
        __syncthreads();
    }
}

// ============================================================
extern "C" void kernel_launch(void* const* d_in, const int* in_sizes, int n_in,
                              void* d_out, int out_size)
{
    const float* x     = (const float*)d_in[0];
    const float* fg    = (const float*)d_in[1];
    const float* bg    = (const float*)d_in[2];
    const float* Wq    = (const float*)d_in[3];
    const float* bq    = (const float*)d_in[4];
    const float* Wk    = (const float*)d_in[5];
    const float* bk    = (const float*)d_in[6];
    const float* gamma = (const float*)d_in[7];
    float* out = (float*)d_out;

    vprep<<<B_ * C_, 256>>>(x);
    proj_t<<<dim3(14, 2, 32), 256>>>(Wq, bq, Wk, bk);
    sim_t<<<dim3(14, 14, 16), 256>>>(fg);
    xform<<<B_ * N_, 256>>>(fg, bg);
    ctx_t<<<dim3(14, 4, 16), 256>>>(x, gamma, out);
}

// round 13
// speedup vs baseline: 1.8018x; 1.2417x over previous
#include <cuda_runtime.h>
#include <cuda_fp16.h>

#define B_    16
#define C_    512
#define N_    1681
#define CK_   256
#define MPQ_  1792          // Q/K n-padding (14*128)
#define MP2_  1728          // attention m-padding (54*32)
#define XP_   1792          // x-split padding
#define NTT_  14
#define SCALE_ 0.0625f
#define EPS_  1e-5f

// ---------------- device scratch (all fp16 operands) ----------------
__device__ __half g_Qh[(size_t)B_*CK_*MPQ_];
__device__ __half g_Kh[(size_t)B_*CK_*MPQ_];
__device__ __half g_Xh[(size_t)B_*C_*XP_], g_Xl[(size_t)B_*C_*XP_];
__device__ __half g_Sb[(size_t)B_*N_*MP2_];
__device__ __half g_Ah[(size_t)B_*N_*MP2_];
__device__ float g_pmin[B_*NTT_*N_], g_pss[B_*NTT_*N_], g_pfs[B_*NTT_*N_];

// ---------------- helpers ----------------
__device__ __forceinline__ unsigned s2u(const void* p) {
    unsigned a;
    asm("{ .reg .u64 t; cvta.to.shared.u64 t, %1; cvt.u32.u64 %0, t; }" : "=r"(a) : "l"(p));
    return a;
}
__device__ __forceinline__ void ldsm4(unsigned* r, unsigned a) {
    asm volatile("ldmatrix.sync.aligned.m8n8.x4.shared.b16 {%0,%1,%2,%3}, [%4];"
                 : "=r"(r[0]), "=r"(r[1]), "=r"(r[2]), "=r"(r[3]) : "r"(a));
}
__device__ __forceinline__ void ldsm4t(unsigned* r, unsigned a) {
    asm volatile("ldmatrix.sync.aligned.m8n8.x4.trans.shared.b16 {%0,%1,%2,%3}, [%4];"
                 : "=r"(r[0]), "=r"(r[1]), "=r"(r[2]), "=r"(r[3]) : "r"(a));
}
__device__ __forceinline__ void mma_h(float* c, const unsigned* a, unsigned b0, unsigned b1) {
    asm volatile("mma.sync.aligned.m16n8k16.row.col.f32.f16.f16.f32 "
                 "{%0,%1,%2,%3}, {%4,%5,%6,%7}, {%8,%9}, {%0,%1,%2,%3};"
                 : "+f"(c[0]), "+f"(c[1]), "+f"(c[2]), "+f"(c[3])
                 : "r"(a[0]), "r"(a[1]), "r"(a[2]), "r"(a[3]), "r"(b0), "r"(b1));
}
// direct tile: [row128][kd32] fp16, stride 80B. trans tile: [kd32][col128] fp16, stride 272B.
__device__ __forceinline__ void ldA_dir(unsigned* a, unsigned tb, int mb, int ks, int L) {
    int q = L >> 3, rs = L & 7;
    ldsm4(a, tb + (unsigned)((mb + (q & 1) * 8 + rs) * 80 + (ks * 2 + (q >> 1)) * 16));
}
__device__ __forceinline__ void ldA_trn(unsigned* a, unsigned tb, int mb, int ks, int L) {
    int q = L >> 3, rs = L & 7;
    ldsm4t(a, tb + (unsigned)((ks * 16 + (q >> 1) * 8 + rs) * 272 + (mb + (q & 1) * 8) * 2));
}
__device__ __forceinline__ void ldB_dir(unsigned* b, unsigned tb, int nb, int ks, int L) {
    int q = L >> 3, rs = L & 7;
    ldsm4(b, tb + (unsigned)((nb + (q >> 1) * 8 + rs) * 80 + (ks * 2 + (q & 1)) * 16));
}
__device__ __forceinline__ void ldB_trn(unsigned* b, unsigned tb, int nb, int ks, int L) {
    int q = L >> 3, rs = L & 7;
    ldsm4t(b, tb + (unsigned)((ks * 16 + (q & 1) * 8 + rs) * 272 + (nb + (q >> 1) * 8) * 2));
}
__device__ __forceinline__ unsigned pack_h2(float a0, float a1) {
    __half2 h;
    h.x = __float2half_rn(a0); h.y = __float2half_rn(a1);
    return *(unsigned*)&h;
}
__device__ __forceinline__ void split_h(float a0, float a1, unsigned& hi, unsigned& lo) {
    __half2 h, l;
    h.x = __float2half_rn(a0); h.y = __float2half_rn(a1);
    l.x = __float2half_rn(a0 - __half2float(h.x));
    l.y = __float2half_rn(a1 - __half2float(h.y));
    hi = *(unsigned*)&h; lo = *(unsigned*)&l;
}

// 1-product chunk, kd=32
template<int AT, int BT>
__device__ __forceinline__ void gemm_chunk1(float (*acc)[4][4], unsigned ah,
                                            unsigned bh, int wm, int wn, int L)
{
    #pragma unroll
    for (int ks = 0; ks < 2; ks++) {
        unsigned aH[16], bH[8];
        #pragma unroll
        for (int fm = 0; fm < 4; fm++) {
            if (AT) ldA_trn(aH + fm*4, ah, wm * 64 + fm * 16, ks, L);
            else    ldA_dir(aH + fm*4, ah, wm * 64 + fm * 16, ks, L);
        }
        #pragma unroll
        for (int fp = 0; fp < 2; fp++) {
            if (BT) ldB_trn(bH + fp*4, bh, wn * 32 + fp * 16, ks, L);
            else    ldB_dir(bH + fp*4, bh, wn * 32 + fp * 16, ks, L);
        }
        #pragma unroll
        for (int fm = 0; fm < 4; fm++)
            #pragma unroll
            for (int fn = 0; fn < 4; fn++) {
                int bi = (fn >> 1) * 4 + (fn & 1) * 2;
                mma_h(acc[fm][fn], aH + fm*4, bH[bi], bH[bi+1]);
            }
    }
}

// 2-product chunk (A single, B hi/lo), dir/dir, kd=32
__device__ __forceinline__ void gemm_chunk2(float (*acc)[4][4], unsigned ah,
                                            unsigned bh, unsigned bl, int wm, int wn, int L)
{
    #pragma unroll
    for (int ks = 0; ks < 2; ks++) {
        unsigned aH[16], bH[8], bL[8];
        #pragma unroll
        for (int fm = 0; fm < 4; fm++)
            ldA_dir(aH + fm*4, ah, wm * 64 + fm * 16, ks, L);
        #pragma unroll
        for (int fp = 0; fp < 2; fp++) {
            ldB_dir(bH + fp*4, bh, wn * 32 + fp * 16, ks, L);
            ldB_dir(bL + fp*4, bl, wn * 32 + fp * 16, ks, L);
        }
        #pragma unroll
        for (int fm = 0; fm < 4; fm++)
            #pragma unroll
            for (int fn = 0; fn < 4; fn++) {
                int bi = (fn >> 1) * 4 + (fn & 1) * 2;
                mma_h(acc[fm][fn], aH + fm*4, bH[bi], bH[bi+1]);
                mma_h(acc[fm][fn], aH + fm*4, bL[bi], bL[bi+1]);
            }
    }
}

// ============ vprep: split x into padded fp16 hi/lo [b][c][XP_], vectorized stores ============
__global__ __launch_bounds__(256)
void vprep(const float* __restrict__ x)
{
    int row = blockIdx.x;                 // b*C + c
    size_t xb = (size_t)row * N_, ob = (size_t)row * XP_;
    for (int g = threadIdx.x; g < XP_ / 4; g += 256) {
        int m = g * 4;
        float v[4];
        #pragma unroll
        for (int e = 0; e < 4; e++)
            v[e] = (m + e < N_) ? __ldg(x + xb + m + e) : 0.f;
        unsigned h01, l01, h23, l23;
        split_h(v[0], v[1], h01, l01);
        split_h(v[2], v[3], h23, l23);
        *(uint2*)(g_Xh + ob + m) = make_uint2(h01, h23);
        *(uint2*)(g_Xl + ob + m) = make_uint2(l01, l23);
    }
}

// ============ proj: D[k,n] = W@x + b (1-product fp16), store [b][k][n-pad] ============
__global__ __launch_bounds__(256, 2)
void proj_t(const float* __restrict__ Wq, const float* __restrict__ bq,
            const float* __restrict__ Wk, const float* __restrict__ bk)
{
    __shared__ __align__(16) char sm[10240 + 8704];
    unsigned sA = s2u(sm), sB = sA + 10240;
    int t = threadIdx.x, L = t & 31, w = t >> 5, wm = w & 1, wn = w >> 1;
    int z = blockIdx.z, b = z >> 1, isK = z & 1;
    const float* W    = isK ? Wk : Wq;
    const float* bias = isK ? bk : bq;
    __half* Oh = isK ? g_Kh : g_Qh;
    int n0 = blockIdx.x * 128, k0 = blockIdx.y * 128;
    const __half* Xh = g_Xh + (size_t)b * C_ * XP_;

    float acc[4][4][4] = {};
    for (int c0 = 0; c0 < C_; c0 += 32) {
        {   // A = W rows k -> fp16 hi
            int r = t >> 1, hf = t & 1;
            const float4* Wp = (const float4*)(W + (size_t)(k0 + r) * C_ + c0 + hf * 16);
            unsigned hi[8];
            #pragma unroll
            for (int v = 0; v < 4; v++) {
                float4 f = Wp[v];
                hi[2*v]   = pack_h2(f.x, f.y);
                hi[2*v+1] = pack_h2(f.z, f.w);
            }
            unsigned off = r * 80 + hf * 32;
            *(uint4*)(sm + off)      = ((uint4*)hi)[0];
            *(uint4*)(sm + off + 16) = ((uint4*)hi)[1];
        }
        {   // B = x rows c, trans layout — uint4 copies from pre-split hi
            int r = t >> 3, seg = t & 7;
            size_t src = (size_t)(c0 + r) * XP_ + n0 + seg * 16;
            unsigned off = 10240 + r * 272 + seg * 32;
            *(uint4*)(sm + off)      = *(const uint4*)(Xh + src);
            *(uint4*)(sm + off + 16) = *(const uint4*)(Xh + src + 8);
        }
        __syncthreads();
        gemm_chunk1<0, 1>(acc, sA, sB, wm, wn, L);
        __syncthreads();
    }
    #pragma unroll
    for (int fm = 0; fm < 4; fm++) {
        #pragma unroll
        for (int rh = 0; rh < 2; rh++) {
            int k = k0 + wm * 64 + fm * 16 + (L >> 2) + rh * 8;
            float bia = bias[k];
            #pragma unroll
            for (int fn = 0; fn < 4; fn++) {
                int n = n0 + wn * 32 + fn * 8 + 2 * (L & 3);
                unsigned hp = pack_h2(acc[fm][fn][rh*2] + bia, acc[fm][fn][rh*2+1] + bia);
                *(unsigned*)(Oh + ((size_t)b * CK_ + k) * MPQ_ + n) = hp;
            }
        }
    }
}

// ============ sim: Sb[n,m] = fp16((Q.K^T)*scale*fg) + row stats (1-product fp16) ============
__global__ __launch_bounds__(256, 2)
void sim_t(const float* __restrict__ fg)
{
    __shared__ __align__(16) char sm[17408 + 6144];
    unsigned sQ = s2u(sm), sK = sQ + 8704;
    float* red = (float*)(sm + 17408);     // [3][8][64]
    int t = threadIdx.x, L = t & 31, w = t >> 5, wm = w & 1, wn = w >> 1;
    int b = blockIdx.z, m0 = blockIdx.x * 128, n0 = blockIdx.y * 128;

    float acc[4][4][4] = {};
    for (int k0 = 0; k0 < CK_; k0 += 32) {
        int r = t >> 3, seg = t & 7;
        size_t qi = ((size_t)b * CK_ + k0 + r) * MPQ_ + n0 + seg * 16;
        size_t ki = ((size_t)b * CK_ + k0 + r) * MPQ_ + m0 + seg * 16;
        unsigned off = r * 272 + seg * 32;
        *(uint4*)(sm + off)             = *(const uint4*)(g_Qh + qi);
        *(uint4*)(sm + off + 16)        = *(const uint4*)(g_Qh + qi + 8);
        *(uint4*)(sm + 8704 + off)      = *(const uint4*)(g_Kh + ki);
        *(uint4*)(sm + 8704 + off + 16) = *(const uint4*)(g_Kh + ki + 8);
        __syncthreads();
        gemm_chunk1<1, 1>(acc, sQ, sK, wm, wn, L);
        __syncthreads();
    }

    float rmn[4][2], rss[4][2], rfs[4][2];
    #pragma unroll
    for (int fm = 0; fm < 4; fm++)
        #pragma unroll
        for (int rh = 0; rh < 2; rh++) { rmn[fm][rh] = 3.4e38f; rss[fm][rh] = 0.f; rfs[fm][rh] = 0.f; }

    #pragma unroll
    for (int fm = 0; fm < 4; fm++)
        #pragma unroll
        for (int rh = 0; rh < 2; rh++) {
            int n = n0 + wm * 64 + fm * 16 + (L >> 2) + rh * 8;
            if (n < N_) {
                size_t fb = (size_t)b * N_ * N_ + (size_t)n * N_;
                size_t sbv = (size_t)b * N_ * MP2_ + (size_t)n * MP2_;
                #pragma unroll
                for (int fn = 0; fn < 4; fn++) {
                    int m = m0 + wn * 32 + fn * 8 + 2 * (L & 3);
                    float s0 = 0.f, s1v = 0.f;
                    if (m < N_) {
                        float f = __ldg(fg + fb + m);
                        s0 = acc[fm][fn][rh*2] * SCALE_ * f;
                        rmn[fm][rh] = fminf(rmn[fm][rh], s0);
                        rss[fm][rh] += s0 * f;
                        rfs[fm][rh] += f;
                    }
                    if (m + 1 < N_) {
                        float f = __ldg(fg + fb + m + 1);
                        s1v = acc[fm][fn][rh*2+1] * SCALE_ * f;
                        rmn[fm][rh] = fminf(rmn[fm][rh], s1v);
                        rss[fm][rh] += s1v * f;
                        rfs[fm][rh] += f;
                    }
                    if (m < N_)
                        *(unsigned*)(g_Sb + sbv + m) = pack_h2(s0, s1v);
                }
            }
        }
    #pragma unroll
    for (int fm = 0; fm < 4; fm++)
        #pragma unroll
        for (int rh = 0; rh < 2; rh++) {
            #pragma unroll
            for (int xr = 1; xr < 4; xr <<= 1) {
                rmn[fm][rh] = fminf(rmn[fm][rh], __shfl_xor_sync(0xFFFFFFFFu, rmn[fm][rh], xr));
                rss[fm][rh] += __shfl_xor_sync(0xFFFFFFFFu, rss[fm][rh], xr);
                rfs[fm][rh] += __shfl_xor_sync(0xFFFFFFFFu, rfs[fm][rh], xr);
            }
            if ((L & 3) == 0) {
                int ri = w * 64 + fm * 16 + rh * 8 + (L >> 2);
                red[ri] = rmn[fm][rh];
                red[512 + ri] = rss[fm][rh];
                red[1024 + ri] = rfs[fm][rh];
            }
        }
    __syncthreads();
    if (t < 128) {
        int hf = t >> 6, row = t & 63;
        float mn = 3.4e38f, ss = 0.f, fs = 0.f;
        #pragma unroll
        for (int j = 0; j < 4; j++) {
            int ww = hf + 2 * j;
            mn = fminf(mn, red[ww * 64 + row]);
            ss += red[512 + ww * 64 + row];
            fs += red[1024 + ww * 64 + row];
        }
        int n = n0 + hf * 64 + row;
        if (n < N_) {
            size_t idx = ((size_t)b * NTT_ + blockIdx.x) * N_ + n;
            g_pmin[idx] = mn; g_pss[idx] = ss; g_pfs[idx] = fs;
        }
    }
}

// ============ xform: finalize stats + A = fp16((Sb-min)*fg*inv + bg) ============
__global__ __launch_bounds__(256)
void xform(const float* __restrict__ fg, const float* __restrict__ bg)
{
    __shared__ float s_mn, s_iv;
    int r = blockIdx.x;               // b*N_ + n
    int t = threadIdx.x;
    int b = r / N_, n = r - b * N_;
    if (t < 32) {
        float mn = 3.4e38f, ss = 0.f, fs = 0.f;
        if (t < NTT_) {
            size_t idx = ((size_t)b * NTT_ + t) * N_ + n;
            mn = g_pmin[idx]; ss = g_pss[idx]; fs = g_pfs[idx];
        }
        #pragma unroll
        for (int xr = 16; xr > 0; xr >>= 1) {
            mn = fminf(mn, __shfl_xor_sync(0xFFFFFFFFu, mn, xr));
            ss += __shfl_xor_sync(0xFFFFFFFFu, ss, xr);
            fs += __shfl_xor_sync(0xFFFFFFFFu, fs, xr);
        }
        if (t == 0) { s_mn = mn; s_iv = 1.f / ((ss - mn * fs) + EPS_); }
    }
    __syncthreads();
    float mn = s_mn, iv = s_iv;
    size_t sbase = (size_t)r * MP2_;
    size_t gbase = (size_t)r * N_;
    for (int g = t; g < MP2_ / 4; g += 256) {
        int m = g * 4;
        float a[4];
        if (g < 420) {
            uint2 sp = *(const uint2*)(g_Sb + sbase + m);
            __half2 s01 = *(__half2*)&sp.x;
            __half2 s23 = *(__half2*)&sp.y;
            float sv[4] = { __half2float(s01.x), __half2float(s01.y),
                            __half2float(s23.x), __half2float(s23.y) };
            #pragma unroll
            for (int e = 0; e < 4; e++)
                a[e] = (sv[e] - mn) * __ldg(fg + gbase + m + e) * iv + __ldg(bg + gbase + m + e);
        } else if (g == 420) {
            #pragma unroll
            for (int e = 0; e < 4; e++) {
                int mm = m + e;
                if (mm < N_) {
                    float s1 = __half2float(g_Sb[sbase + mm]);
                    a[e] = (s1 - mn) * __ldg(fg + gbase + mm) * iv + __ldg(bg + gbase + mm);
                } else a[e] = 0.f;
            }
        } else {
            a[0] = a[1] = a[2] = a[3] = 0.f;
        }
        *(uint2*)(g_Ah + sbase + m) = make_uint2(pack_h2(a[0], a[1]), pack_h2(a[2], a[3]));
    }
}

// ============ ctx: out[c,n] = gamma*(attn @ x^T)[n,c] + x[c,n] (2-product fp16) ============
__global__ __launch_bounds__(256, 2)
void ctx_t(const float* __restrict__ x, const float* __restrict__ gamma,
           float* __restrict__ out)
{
    __shared__ __align__(16) char sm[34816];
    unsigned sA = s2u(sm), sBh = sA + 10240, sBl = sA + 20480;
    int t = threadIdx.x, L = t & 31, w = t >> 5, wm = w & 1, wn = w >> 1;
    int b = blockIdx.z, n0 = blockIdx.x * 128, c0 = blockIdx.y * 128;
    const __half* Xh = g_Xh + (size_t)b * C_ * XP_;
    const __half* Xl = g_Xl + (size_t)b * C_ * XP_;

    float acc[4][4][4] = {};
    for (int m0 = 0; m0 < MP2_; m0 += 32) {
        int r = t >> 1, hf = t & 1;
        {   // A = attn rows n (uint4, zero-pad n>=N rows)
            int n = n0 + r;
            unsigned off = r * 80 + hf * 32;
            if (n < N_) {
                size_t ai = ((size_t)b * N_ + n) * MP2_ + m0 + hf * 16;
                *(uint4*)(sm + off)      = *(const uint4*)(g_Ah + ai);
                *(uint4*)(sm + off + 16) = *(const uint4*)(g_Ah + ai + 8);
            } else {
                uint4 z = make_uint4(0, 0, 0, 0);
                *(uint4*)(sm + off) = z; *(uint4*)(sm + off + 16) = z;
            }
        }
        {   // B = x rows c — uint4 copies from pre-split hi/lo
            size_t src = (size_t)(c0 + r) * XP_ + m0 + hf * 16;
            unsigned off = 10240 + r * 80 + hf * 32;
            *(uint4*)(sm + off)              = *(const uint4*)(Xh + src);
            *(uint4*)(sm + off + 16)         = *(const uint4*)(Xh + src + 8);
            *(uint4*)(sm + 10240 + off)      = *(const uint4*)(Xl + src);
            *(uint4*)(sm + 10240 + off + 16) = *(const uint4*)(Xl + src + 8);
        }
        __syncthreads();
        gemm_chunk2(acc, sA, sBh, sBl, wm, wn, L);
        __syncthreads();
    }

    float gam = __ldg(gamma);
    float* stage = (float*)sm;
    #pragma unroll 1
    for (int ch = 0; ch < 2; ch++) {
        if ((wn >> 1) == ch) {
            #pragma unroll
            for (int fm = 0; fm < 4; fm++)
                #pragma unroll
                for (int fn = 0; fn < 4; fn++)
                    #pragma unroll
                    for (int e = 0; e < 4; e++) {
                        int cl = (wn & 1) * 32 + fn * 8 + 2 * (L & 3) + (e & 1);
                        int nl = wm * 64 + fm * 16 + (L >> 2) + (e >> 1) * 8;
                        stage[cl * 132 + nl] = acc[fm][fn][e];
                    }
        }
        __syncthreads();
        #pragma unroll 1
        for (int rr = 0; rr < 8; rr++) {
            int cc = w * 8 + rr;
            int c = c0 + ch * 64 + cc;
            size_t ob = ((size_t)b * C_ + c) * N_;
            #pragma unroll
            for (int jj = 0; jj < 4; jj++) {
                int n = n0 + jj * 32 + L;
                if (n < N_)
                    out[ob + n] = gam * stage[cc * 132 + jj * 32 + L] + __ldg(x + ob + n);
            }
        }
        __syncthreads();
    }
}

// ============================================================
extern "C" void kernel_launch(void* const* d_in, const int* in_sizes, int n_in,
                              void* d_out, int out_size)
{
    const float* x     = (const float*)d_in[0];
    const float* fg    = (const float*)d_in[1];
    const float* bg    = (const float*)d_in[2];
    const float* Wq    = (const float*)d_in[3];
    const float* bq    = (const float*)d_in[4];
    const float* Wk    = (const float*)d_in[5];
    const float* bk    = (const float*)d_in[6];
    const float* gamma = (const float*)d_in[7];
    float* out = (float*)d_out;

    vprep<<<B_ * C_, 256>>>(x);
    proj_t<<<dim3(14, 2, 32), 256>>>(Wq, bq, Wk, bk);
    sim_t<<<dim3(14, 14, 16), 256>>>(fg);
    xform<<<B_ * N_, 256>>>(fg, bg);
    ctx_t<<<dim3(14, 4, 16), 256>>>(x, gamma, out);
}

// round 14
// speedup vs baseline: 2.1245x; 1.1791x over previous
#include <cuda_runtime.h>
#include <cuda_fp16.h>

#define B_    16
#define C_    512
#define N_    1681
#define CK_   256
#define MPQ_  1792          // Q/K n-padding (14*128)
#define MP2_  1728          // attention m-padding (54*32)
#define XP_   1792          // x-split padding
#define NTT_  14
#define SCALE_ 0.0625f
#define EPS_  1e-5f

// ---------------- device scratch (all fp16 operands) ----------------
__device__ __half g_Qh[(size_t)B_*CK_*MPQ_];
__device__ __half g_Kh[(size_t)B_*CK_*MPQ_];
__device__ __half g_Xh[(size_t)B_*C_*XP_];
__device__ __half g_Sb[(size_t)B_*N_*MP2_];
__device__ __half g_Ah[(size_t)B_*N_*MP2_];
__device__ float g_pmin[B_*NTT_*N_], g_pss[B_*NTT_*N_], g_pfs[B_*NTT_*N_];

// ---------------- helpers ----------------
__device__ __forceinline__ unsigned s2u(const void* p) {
    unsigned a;
    asm("{ .reg .u64 t; cvta.to.shared.u64 t, %1; cvt.u32.u64 %0, t; }" : "=r"(a) : "l"(p));
    return a;
}
__device__ __forceinline__ void ldsm4(unsigned* r, unsigned a) {
    asm volatile("ldmatrix.sync.aligned.m8n8.x4.shared.b16 {%0,%1,%2,%3}, [%4];"
                 : "=r"(r[0]), "=r"(r[1]), "=r"(r[2]), "=r"(r[3]) : "r"(a));
}
__device__ __forceinline__ void ldsm4t(unsigned* r, unsigned a) {
    asm volatile("ldmatrix.sync.aligned.m8n8.x4.trans.shared.b16 {%0,%1,%2,%3}, [%4];"
                 : "=r"(r[0]), "=r"(r[1]), "=r"(r[2]), "=r"(r[3]) : "r"(a));
}
__device__ __forceinline__ void mma_h(float* c, const unsigned* a, unsigned b0, unsigned b1) {
    asm volatile("mma.sync.aligned.m16n8k16.row.col.f32.f16.f16.f32 "
                 "{%0,%1,%2,%3}, {%4,%5,%6,%7}, {%8,%9}, {%0,%1,%2,%3};"
                 : "+f"(c[0]), "+f"(c[1]), "+f"(c[2]), "+f"(c[3])
                 : "r"(a[0]), "r"(a[1]), "r"(a[2]), "r"(a[3]), "r"(b0), "r"(b1));
}
// direct tile: [row128][kd32] fp16, stride 80B. trans tile: [kd32][col128] fp16, stride 272B.
__device__ __forceinline__ void ldA_dir(unsigned* a, unsigned tb, int mb, int ks, int L) {
    int q = L >> 3, rs = L & 7;
    ldsm4(a, tb + (unsigned)((mb + (q & 1) * 8 + rs) * 80 + (ks * 2 + (q >> 1)) * 16));
}
__device__ __forceinline__ void ldA_trn(unsigned* a, unsigned tb, int mb, int ks, int L) {
    int q = L >> 3, rs = L & 7;
    ldsm4t(a, tb + (unsigned)((ks * 16 + (q >> 1) * 8 + rs) * 272 + (mb + (q & 1) * 8) * 2));
}
__device__ __forceinline__ void ldB_dir(unsigned* b, unsigned tb, int nb, int ks, int L) {
    int q = L >> 3, rs = L & 7;
    ldsm4(b, tb + (unsigned)((nb + (q >> 1) * 8 + rs) * 80 + (ks * 2 + (q & 1)) * 16));
}
__device__ __forceinline__ void ldB_trn(unsigned* b, unsigned tb, int nb, int ks, int L) {
    int q = L >> 3, rs = L & 7;
    ldsm4t(b, tb + (unsigned)((ks * 16 + (q & 1) * 8 + rs) * 272 + (nb + (q >> 1) * 8) * 2));
}
__device__ __forceinline__ unsigned pack_h2(float a0, float a1) {
    __half2 h;
    h.x = __float2half_rn(a0); h.y = __float2half_rn(a1);
    return *(unsigned*)&h;
}

// 1-product chunk, kd=32
template<int AT, int BT>
__device__ __forceinline__ void gemm_chunk1(float (*acc)[4][4], unsigned ah,
                                            unsigned bh, int wm, int wn, int L)
{
    #pragma unroll
    for (int ks = 0; ks < 2; ks++) {
        unsigned aH[16], bH[8];
        #pragma unroll
        for (int fm = 0; fm < 4; fm++) {
            if (AT) ldA_trn(aH + fm*4, ah, wm * 64 + fm * 16, ks, L);
            else    ldA_dir(aH + fm*4, ah, wm * 64 + fm * 16, ks, L);
        }
        #pragma unroll
        for (int fp = 0; fp < 2; fp++) {
            if (BT) ldB_trn(bH + fp*4, bh, wn * 32 + fp * 16, ks, L);
            else    ldB_dir(bH + fp*4, bh, wn * 32 + fp * 16, ks, L);
        }
        #pragma unroll
        for (int fm = 0; fm < 4; fm++)
            #pragma unroll
            for (int fn = 0; fn < 4; fn++) {
                int bi = (fn >> 1) * 4 + (fn & 1) * 2;
                mma_h(acc[fm][fn], aH + fm*4, bH[bi], bH[bi+1]);
            }
    }
}

// ============ vprep: x -> padded fp16 [b][c][XP_], vectorized ============
__global__ __launch_bounds__(256)
void vprep(const float* __restrict__ x)
{
    int row = blockIdx.x;                 // b*C + c
    size_t xb = (size_t)row * N_, ob = (size_t)row * XP_;
    for (int g = threadIdx.x; g < XP_ / 4; g += 256) {
        int m = g * 4;
        float v[4];
        #pragma unroll
        for (int e = 0; e < 4; e++)
            v[e] = (m + e < N_) ? __ldg(x + xb + m + e) : 0.f;
        *(uint2*)(g_Xh + ob + m) = make_uint2(pack_h2(v[0], v[1]), pack_h2(v[2], v[3]));
    }
}

// ============ proj: D[k,n] = W@x + b (1-product fp16), store [b][k][n-pad] ============
__global__ __launch_bounds__(256, 2)
void proj_t(const float* __restrict__ Wq, const float* __restrict__ bq,
            const float* __restrict__ Wk, const float* __restrict__ bk)
{
    __shared__ __align__(16) char sm[10240 + 8704];
    unsigned sA = s2u(sm), sB = sA + 10240;
    int t = threadIdx.x, L = t & 31, w = t >> 5, wm = w & 1, wn = w >> 1;
    int z = blockIdx.z, b = z >> 1, isK = z & 1;
    const float* W    = isK ? Wk : Wq;
    const float* bias = isK ? bk : bq;
    __half* Oh = isK ? g_Kh : g_Qh;
    int n0 = blockIdx.x * 128, k0 = blockIdx.y * 128;
    const __half* Xh = g_Xh + (size_t)b * C_ * XP_;

    float acc[4][4][4] = {};
    for (int c0 = 0; c0 < C_; c0 += 32) {
        {   // A = W rows k -> fp16
            int r = t >> 1, hf = t & 1;
            const float4* Wp = (const float4*)(W + (size_t)(k0 + r) * C_ + c0 + hf * 16);
            unsigned hi[8];
            #pragma unroll
            for (int v = 0; v < 4; v++) {
                float4 f = Wp[v];
                hi[2*v]   = pack_h2(f.x, f.y);
                hi[2*v+1] = pack_h2(f.z, f.w);
            }
            unsigned off = r * 80 + hf * 32;
            *(uint4*)(sm + off)      = ((uint4*)hi)[0];
            *(uint4*)(sm + off + 16) = ((uint4*)hi)[1];
        }
        {   // B = x rows c, trans layout — uint4 copies from pre-split
            int r = t >> 3, seg = t & 7;
            size_t src = (size_t)(c0 + r) * XP_ + n0 + seg * 16;
            unsigned off = 10240 + r * 272 + seg * 32;
            *(uint4*)(sm + off)      = *(const uint4*)(Xh + src);
            *(uint4*)(sm + off + 16) = *(const uint4*)(Xh + src + 8);
        }
        __syncthreads();
        gemm_chunk1<0, 1>(acc, sA, sB, wm, wn, L);
        __syncthreads();
    }
    #pragma unroll
    for (int fm = 0; fm < 4; fm++) {
        #pragma unroll
        for (int rh = 0; rh < 2; rh++) {
            int k = k0 + wm * 64 + fm * 16 + (L >> 2) + rh * 8;
            float bia = bias[k];
            #pragma unroll
            for (int fn = 0; fn < 4; fn++) {
                int n = n0 + wn * 32 + fn * 8 + 2 * (L & 3);
                unsigned hp = pack_h2(acc[fm][fn][rh*2] + bia, acc[fm][fn][rh*2+1] + bia);
                *(unsigned*)(Oh + ((size_t)b * CK_ + k) * MPQ_ + n) = hp;
            }
        }
    }
}

// ============ sim: Sb[n,m] = fp16((Q.K^T)*scale*fg) + row stats (1-product fp16) ============
__global__ __launch_bounds__(256, 2)
void sim_t(const float* __restrict__ fg)
{
    __shared__ __align__(16) char sm[17408 + 6144];
    unsigned sQ = s2u(sm), sK = sQ + 8704;
    float* red = (float*)(sm + 17408);     // [3][8][64]
    int t = threadIdx.x, L = t & 31, w = t >> 5, wm = w & 1, wn = w >> 1;
    int b = blockIdx.z, m0 = blockIdx.x * 128, n0 = blockIdx.y * 128;

    float acc[4][4][4] = {};
    for (int k0 = 0; k0 < CK_; k0 += 32) {
        int r = t >> 3, seg = t & 7;
        size_t qi = ((size_t)b * CK_ + k0 + r) * MPQ_ + n0 + seg * 16;
        size_t ki = ((size_t)b * CK_ + k0 + r) * MPQ_ + m0 + seg * 16;
        unsigned off = r * 272 + seg * 32;
        *(uint4*)(sm + off)             = *(const uint4*)(g_Qh + qi);
        *(uint4*)(sm + off + 16)        = *(const uint4*)(g_Qh + qi + 8);
        *(uint4*)(sm + 8704 + off)      = *(const uint4*)(g_Kh + ki);
        *(uint4*)(sm + 8704 + off + 16) = *(const uint4*)(g_Kh + ki + 8);
        __syncthreads();
        gemm_chunk1<1, 1>(acc, sQ, sK, wm, wn, L);
        __syncthreads();
    }

    float rmn[4][2], rss[4][2], rfs[4][2];
    #pragma unroll
    for (int fm = 0; fm < 4; fm++)
        #pragma unroll
        for (int rh = 0; rh < 2; rh++) { rmn[fm][rh] = 3.4e38f; rss[fm][rh] = 0.f; rfs[fm][rh] = 0.f; }

    #pragma unroll
    for (int fm = 0; fm < 4; fm++)
        #pragma unroll
        for (int rh = 0; rh < 2; rh++) {
            int n = n0 + wm * 64 + fm * 16 + (L >> 2) + rh * 8;
            if (n < N_) {
                size_t fb = (size_t)b * N_ * N_ + (size_t)n * N_;
                size_t sbv = (size_t)b * N_ * MP2_ + (size_t)n * MP2_;
                #pragma unroll
                for (int fn = 0; fn < 4; fn++) {
                    int m = m0 + wn * 32 + fn * 8 + 2 * (L & 3);
                    float s0 = 0.f, s1v = 0.f;
                    if (m < N_) {
                        float f = __ldg(fg + fb + m);
                        s0 = acc[fm][fn][rh*2] * SCALE_ * f;
                        rmn[fm][rh] = fminf(rmn[fm][rh], s0);
                        rss[fm][rh] += s0 * f;
                        rfs[fm][rh] += f;
                    }
                    if (m + 1 < N_) {
                        float f = __ldg(fg + fb + m + 1);
                        s1v = acc[fm][fn][rh*2+1] * SCALE_ * f;
                        rmn[fm][rh] = fminf(rmn[fm][rh], s1v);
                        rss[fm][rh] += s1v * f;
                        rfs[fm][rh] += f;
                    }
                    if (m < N_)
                        *(unsigned*)(g_Sb + sbv + m) = pack_h2(s0, s1v);
                }
            }
        }
    #pragma unroll
    for (int fm = 0; fm < 4; fm++)
        #pragma unroll
        for (int rh = 0; rh < 2; rh++) {
            #pragma unroll
            for (int xr = 1; xr < 4; xr <<= 1) {
                rmn[fm][rh] = fminf(rmn[fm][rh], __shfl_xor_sync(0xFFFFFFFFu, rmn[fm][rh], xr));
                rss[fm][rh] += __shfl_xor_sync(0xFFFFFFFFu, rss[fm][rh], xr);
                rfs[fm][rh] += __shfl_xor_sync(0xFFFFFFFFu, rfs[fm][rh], xr);
            }
            if ((L & 3) == 0) {
                int ri = w * 64 + fm * 16 + rh * 8 + (L >> 2);
                red[ri] = rmn[fm][rh];
                red[512 + ri] = rss[fm][rh];
                red[1024 + ri] = rfs[fm][rh];
            }
        }
    __syncthreads();
    if (t < 128) {
        int hf = t >> 6, row = t & 63;
        float mn = 3.4e38f, ss = 0.f, fs = 0.f;
        #pragma unroll
        for (int j = 0; j < 4; j++) {
            int ww = hf + 2 * j;
            mn = fminf(mn, red[ww * 64 + row]);
            ss += red[512 + ww * 64 + row];
            fs += red[1024 + ww * 64 + row];
        }
        int n = n0 + hf * 64 + row;
        if (n < N_) {
            size_t idx = ((size_t)b * NTT_ + blockIdx.x) * N_ + n;
            g_pmin[idx] = mn; g_pss[idx] = ss; g_pfs[idx] = fs;
        }
    }
}

// ============ xform: finalize stats + A = fp16((Sb-min)*fg*inv + bg) ============
__global__ __launch_bounds__(256)
void xform(const float* __restrict__ fg, const float* __restrict__ bg)
{
    __shared__ float s_mn, s_iv;
    int r = blockIdx.x;               // b*N_ + n
    int t = threadIdx.x;
    int b = r / N_, n = r - b * N_;
    if (t < 32) {
        float mn = 3.4e38f, ss = 0.f, fs = 0.f;
        if (t < NTT_) {
            size_t idx = ((size_t)b * NTT_ + t) * N_ + n;
            mn = g_pmin[idx]; ss = g_pss[idx]; fs = g_pfs[idx];
        }
        #pragma unroll
        for (int xr = 16; xr > 0; xr >>= 1) {
            mn = fminf(mn, __shfl_xor_sync(0xFFFFFFFFu, mn, xr));
            ss += __shfl_xor_sync(0xFFFFFFFFu, ss, xr);
            fs += __shfl_xor_sync(0xFFFFFFFFu, fs, xr);
        }
        if (t == 0) { s_mn = mn; s_iv = 1.f / ((ss - mn * fs) + EPS_); }
    }
    __syncthreads();
    float mn = s_mn, iv = s_iv;
    size_t sbase = (size_t)r * MP2_;
    size_t gbase = (size_t)r * N_;
    for (int g = t; g < MP2_ / 4; g += 256) {
        int m = g * 4;
        float a[4];
        if (g < 420) {
            uint2 sp = *(const uint2*)(g_Sb + sbase + m);
            __half2 s01 = *(__half2*)&sp.x;
            __half2 s23 = *(__half2*)&sp.y;
            float sv[4] = { __half2float(s01.x), __half2float(s01.y),
                            __half2float(s23.x), __half2float(s23.y) };
            #pragma unroll
            for (int e = 0; e < 4; e++)
                a[e] = (sv[e] - mn) * __ldg(fg + gbase + m + e) * iv + __ldg(bg + gbase + m + e);
        } else if (g == 420) {
            #pragma unroll
            for (int e = 0; e < 4; e++) {
                int mm = m + e;
                if (mm < N_) {
                    float s1 = __half2float(g_Sb[sbase + mm]);
                    a[e] = (s1 - mn) * __ldg(fg + gbase + mm) * iv + __ldg(bg + gbase + mm);
                } else a[e] = 0.f;
            }
        } else {
            a[0] = a[1] = a[2] = a[3] = 0.f;
        }
        *(uint2*)(g_Ah + sbase + m) = make_uint2(pack_h2(a[0], a[1]), pack_h2(a[2], a[3]));
    }
}

// ============ ctx: out[c,n] = gamma*(attn @ x^T)[n,c] + x[c,n] (1-product fp16) ============
__global__ __launch_bounds__(256, 2)
void ctx_t(const float* __restrict__ x, const float* __restrict__ gamma,
           float* __restrict__ out)
{
    __shared__ __align__(16) char sm[34816];   // epilogue staging needs 33792
    unsigned sA = s2u(sm), sB = sA + 10240;
    int t = threadIdx.x, L = t & 31, w = t >> 5, wm = w & 1, wn = w >> 1;
    int b = blockIdx.z, n0 = blockIdx.x * 128, c0 = blockIdx.y * 128;
    const __half* Xh = g_Xh + (size_t)b * C_ * XP_;

    float acc[4][4][4] = {};
    for (int m0 = 0; m0 < MP2_; m0 += 32) {
        int r = t >> 1, hf = t & 1;
        {   // A = attn rows n (uint4, zero-pad n>=N rows)
            int n = n0 + r;
            unsigned off = r * 80 + hf * 32;
            if (n < N_) {
                size_t ai = ((size_t)b * N_ + n) * MP2_ + m0 + hf * 16;
                *(uint4*)(sm + off)      = *(const uint4*)(g_Ah + ai);
                *(uint4*)(sm + off + 16) = *(const uint4*)(g_Ah + ai + 8);
            } else {
                uint4 z = make_uint4(0, 0, 0, 0);
                *(uint4*)(sm + off) = z; *(uint4*)(sm + off + 16) = z;
            }
        }
        {   // B = x rows c — uint4 copies
            size_t src = (size_t)(c0 + r) * XP_ + m0 + hf * 16;
            unsigned off = 10240 + r * 80 + hf * 32;
            *(uint4*)(sm + off)      = *(const uint4*)(Xh + src);
            *(uint4*)(sm + off + 16) = *(const uint4*)(Xh + src + 8);
        }
        __syncthreads();
        gemm_chunk1<0, 0>(acc, sA, sB, wm, wn, L);
        __syncthreads();
    }

    float gam = __ldg(gamma);
    float* stage = (float*)sm;
    #pragma unroll 1
    for (int ch = 0; ch < 2; ch++) {
        if ((wn >> 1) == ch) {
            #pragma unroll
            for (int fm = 0; fm < 4; fm++)
                #pragma unroll
                for (int fn = 0; fn < 4; fn++)
                    #pragma unroll
                    for (int e = 0; e < 4; e++) {
                        int cl = (wn & 1) * 32 + fn * 8 + 2 * (L & 3) + (e & 1);
                        int nl = wm * 64 + fm * 16 + (L >> 2) + (e >> 1) * 8;
                        stage[cl * 132 + nl] = acc[fm][fn][e];
                    }
        }
        __syncthreads();
        #pragma unroll 1
        for (int rr = 0; rr < 8; rr++) {
            int cc = w * 8 + rr;
            int c = c0 + ch * 64 + cc;
            size_t ob = ((size_t)b * C_ + c) * N_;
            #pragma unroll
            for (int jj = 0; jj < 4; jj++) {
                int n = n0 + jj * 32 + L;
                if (n < N_)
                    out[ob + n] = gam * stage[cc * 132 + jj * 32 + L] + __ldg(x + ob + n);
            }
        }
        __syncthreads();
    }
}

// ============================================================
extern "C" void kernel_launch(void* const* d_in, const int* in_sizes, int n_in,
                              void* d_out, int out_size)
{
    const float* x     = (const float*)d_in[0];
    const float* fg    = (const float*)d_in[1];
    const float* bg    = (const float*)d_in[2];
    const float* Wq    = (const float*)d_in[3];
    const float* bq    = (const float*)d_in[4];
    const float* Wk    = (const float*)d_in[5];
    const float* bk    = (const float*)d_in[6];
    const float* gamma = (const float*)d_in[7];
    float* out = (float*)d_out;

    vprep<<<B_ * C_, 256>>>(x);
    proj_t<<<dim3(14, 2, 32), 256>>>(Wq, bq, Wk, bk);
    sim_t<<<dim3(14, 14, 16), 256>>>(fg);
    xform<<<B_ * N_, 256>>>(fg, bg);
    ctx_t<<<dim3(14, 4, 16), 256>>>(x, gamma, out);
}